// round 6
// baseline (speedup 1.0000x reference)
#include <cuda_runtime.h>
#include <math.h>
#include <stdint.h>

#define BB 4
#define HH 8
#define TT 8192
#define DD 64
#define CC 64
#define WSZ 128
#define BH (BB*HH)
#define NOUT (BB*HH*TT*DD)
#define LOSSP (BH*(TT/256))

// ---------------- scratch (device globals; no allocation) ----------------
__device__ unsigned g_keys[(size_t)BH*CC*TT];   // 64 MB sortable keys
__device__ int      g_idx[BH*CC*WSZ];
__device__ float    g_cnt[BH*TT];
__device__ float    g_losspart[LOSSP];
__device__ uint32_t g_wfrag[HH*WSZ*DD];         // rel_w fragments per h (256 KB)

// ---------------- K0: zero out + cnt ----------------
__global__ void k_zero(float* __restrict__ out) {
    size_t i = (size_t)blockIdx.x * blockDim.x + threadIdx.x;
    if (i < (size_t)(NOUT/4)) ((float4*)out)[i] = make_float4(0.f,0.f,0.f,0.f);
    if (i < (size_t)(BH*TT)) g_cnt[i] = 0.f;
}

__device__ __forceinline__ unsigned fkey(float f) {
    unsigned u = __float_as_uint(f);
    return (u & 0x80000000u) ? ~u : (u | 0x80000000u);
}

// ================= mma.sync helpers (tf32, m16n8k8) =================
__device__ __forceinline__ uint32_t f2tf(float x){
    uint32_t u; asm("cvt.rna.tf32.f32 %0, %1;" : "=r"(u) : "f"(x)); return u;
}
__device__ __forceinline__ void mma8(float c[4], const uint32_t a[4], const uint32_t b[2]){
    asm volatile("mma.sync.aligned.m16n8k8.row.col.f32.tf32.tf32.f32 "
        "{%0,%1,%2,%3}, {%4,%5,%6,%7}, {%8,%9}, {%0,%1,%2,%3};"
        : "+f"(c[0]), "+f"(c[1]), "+f"(c[2]), "+f"(c[3])
        : "r"(a[0]), "r"(a[1]), "r"(a[2]), "r"(a[3]), "r"(b[0]), "r"(b[1]));
}
__device__ __forceinline__ void red2(float* p, float x, float y){
    asm volatile("red.global.add.v2.f32 [%0], {%1,%2};" :: "l"(p), "f"(x), "f"(y) : "memory");
}

// fragment staging index helpers (proven R3/R4)
#define QIDX(r,k) (((((r)>>4)*8 + ((k)>>3))*32 + (((r)&7)*4 + ((k)&3)))*4 + (((r)>>3)&1) + 2*(((k)>>2)&1))
#define KIDX(n,k) (((((n)>>3)*8 + ((k)>>3))*32 + (((n)&7)*4 + ((k)&3)))*2 + (((k)>>2)&1))
#define VIDX(j,d) (((((d)>>3)*16 + ((j)>>3))*32 + (((d)&7)*4 + ((j)&3)))*2 + (((j)>>2)&1))

// ---------------- K1: dists(keys) + loss partials ----------------
__global__ void __launch_bounds__(256) k_dists(const float* __restrict__ qk,
                                               const float* __restrict__ means) {
    int bh = blockIdx.y, h = bh & (HH-1);
    int tid = threadIdx.x;
    __shared__ float ms[CC*DD];
    for (int i = tid; i < CC*DD; i += 256) ms[i] = means[h*CC*DD + i];
    __syncthreads();

    int tok = blockIdx.x*256 + tid;
    const float4* qr = (const float4*)(qk + ((size_t)bh*TT + tok)*DD);
    float q[DD];
    float ss = 0.f;
    #pragma unroll
    for (int f = 0; f < DD/4; f++) {
        float4 a = __ldg(qr + f);
        q[4*f+0]=a.x; q[4*f+1]=a.y; q[4*f+2]=a.z; q[4*f+3]=a.w;
        ss += a.x*a.x + a.y*a.y + a.z*a.z + a.w*a.w;
    }
    float inv = 1.f / fmaxf(sqrtf(ss), 1e-12f);

    float mx = -1e30f;
    unsigned* drow = g_keys + (size_t)bh*CC*TT + tok;
    #pragma unroll 4
    for (int c = 0; c < CC; c++) {
        const float4* m4 = (const float4*)(ms + c*DD);
        float acc = 0.f;
        #pragma unroll
        for (int f = 0; f < DD/4; f++) {
            float4 m = m4[f];
            acc += q[4*f+0]*m.x + q[4*f+1]*m.y + q[4*f+2]*m.z + q[4*f+3]*m.w;
        }
        acc *= inv;
        drow[(size_t)c*TT] = fkey(acc);
        mx = fmaxf(mx, acc);
    }
    float term = ss*inv*inv + 1.0f - 2.0f*mx;

    __shared__ float red[256];
    red[tid] = term; __syncthreads();
    for (int s = 128; s > 0; s >>= 1) { if (tid < s) red[tid] += red[tid+s]; __syncthreads(); }
    if (tid == 0) g_losspart[blockIdx.y*(TT/256) + blockIdx.x] = red[0];
}

// ---------------- K1b: stage rel_w fragments per h ----------------
__global__ void k_wprep(const float* __restrict__ rel_w) {
    int h = blockIdx.x;
    int tid = threadIdx.x;
    int r = tid >> 1, kh = tid & 1, k0 = kh*32;
    const float4* w4 = (const float4*)(rel_w + ((size_t)r*HH + h)*DD + k0);
    uint32_t* dst = g_wfrag + h*(WSZ*DD);
    #pragma unroll
    for (int f = 0; f < 8; f++) {
        float4 wv = __ldg(w4 + f);
        float e[4] = {wv.x, wv.y, wv.z, wv.w};
        #pragma unroll
        for (int u = 0; u < 4; u++) dst[KIDX(r, k0 + 4*f + u)] = f2tf(e[u]);
    }
}

// ---------------- K2: top-128 per (b,h,c), sorted ascending ----------------
#define POFF(t) (((t)>>5)*33 + ((t)&31))
// dynamic smem layout (bytes)
#define TK_KEYS 0                         // (TT/32)*33 u32 = 33792
#define TK_HIST 33792                     // 2048 int   = 8192
#define TK_COAR 41984                     // 256 int    = 1024
#define TK_CA   43008                     // 8192 u16   = 16384
#define TK_CB   59392                     // 8192 u16   = 16384
#define TK_SEL  75776                     // 128 int
#define TK_W    76288                     // wsum/wbase 16 int
#define TK_SMEM 76352

__global__ void __launch_bounds__(256) k_topk() {
    extern __shared__ char tsm[];
    unsigned* keys = (unsigned*)(tsm + TK_KEYS);
    int* hist = (int*)(tsm + TK_HIST);
    int* coarse = (int*)(tsm + TK_COAR);
    unsigned short* candA = (unsigned short*)(tsm + TK_CA);
    unsigned short* candB = (unsigned short*)(tsm + TK_CB);
    int* s_sel = (int*)(tsm + TK_SEL);
    int* wsum = (int*)(tsm + TK_W);
    int* wbase = wsum + 8;
    __shared__ int s_bin, s_above, s_nsel, s_nc;

    int row = blockIdx.x;
    int tid = threadIdx.x;
    int lane = tid & 31, w = tid >> 5;

    for (int x = tid; x < 2048; x += 256) hist[x] = 0;
    if (tid == 0) { s_nsel = 0; s_nc = 0; }
    __syncthreads();

    // fused load + 11-bit histogram
    const unsigned* dr = g_keys + (size_t)row*TT;
    for (int t = tid; t < TT; t += 256) {
        unsigned u = __ldg(dr + t);
        keys[POFF(t)] = u;
        int bin = u >> 21;
        unsigned mk = __match_any_sync(0xFFFFFFFFu, bin);
        if ((int)(__ffs(mk) - 1) == lane) atomicAdd(&hist[bin], __popc(mk));
    }
    __syncthreads();

    int cs = 0;
    #pragma unroll
    for (int e = 0; e < 8; e++) cs += hist[tid*8 + e];
    coarse[tid] = cs;
    __syncthreads();
    int need = WSZ;
    if (tid == 0) {
        int acc = 0, cb = 255;
        for (; cb > 0; cb--) { if (acc + coarse[cb] >= need) break; acc += coarse[cb]; }
        int b = cb*8 + 7;
        for (; b > cb*8; b--) { if (acc + hist[b] >= need) break; acc += hist[b]; }
        s_bin = b; s_above = acc;
    }
    __syncthreads();
    int bin1 = s_bin;
    unsigned prefix = ((unsigned)bin1) << 21;
    need -= s_above;

    // compact: winners straight to sel, threshold-bin to candA
    for (int t = tid; t < TT; t += 256) {
        unsigned u = keys[POFF(t)];
        int bin = u >> 21;
        if (bin > bin1) s_sel[atomicAdd(&s_nsel, 1)] = t;
        else if (bin == bin1) candA[atomicAdd(&s_nc, 1)] = (unsigned short)t;
    }
    __syncthreads();
    int C = s_nc;
    __syncthreads();

    unsigned short* cur = candA;
    unsigned short* nxt = candB;
    const int SH[3] = {13, 5, 0};
    const int MS[3] = {0xFF, 0xFF, 0x1F};
    #pragma unroll
    for (int p = 0; p < 3; p++) {
        if (C == need) break;          // uniform across block
        int sh = SH[p], msk = MS[p];
        if (tid <= msk) hist[tid] = 0;
        if (tid == 0) s_nc = 0;
        __syncthreads();
        for (int x = tid; x < C; x += 256) {
            unsigned u = keys[POFF((int)cur[x])];
            atomicAdd(&hist[(u >> sh) & msk], 1);
        }
        __syncthreads();
        if (tid == 0) {
            int acc = 0, b = msk;
            for (; b > 0; b--) { if (acc + hist[b] >= need) break; acc += hist[b]; }
            s_bin = b; s_above = acc;
        }
        __syncthreads();
        int bb = s_bin;
        prefix |= ((unsigned)bb) << sh;
        need -= s_above;
        for (int x = tid; x < C; x += 256) {
            int t = (int)cur[x];
            unsigned u = keys[POFF(t)];
            int bin = (u >> sh) & msk;
            if (bin > bb) s_sel[atomicAdd(&s_nsel, 1)] = t;
            else if (bin == bb) nxt[atomicAdd(&s_nc, 1)] = (unsigned short)t;
        }
        __syncthreads();
        C = s_nc;
        __syncthreads();
        unsigned short* tp = cur; cur = nxt; nxt = tp;
    }

    if (C == need) {
        for (int x = tid; x < C; x += 256) s_sel[atomicAdd(&s_nsel, 1)] = (int)cur[x];
        __syncthreads();
    } else {
        // rare: exact-duplicate keys == prefix; deterministic smallest-index ranks
        unsigned T = prefix;
        int cnt = 0;
        #pragma unroll 4
        for (int e = 0; e < 32; e++) cnt += (keys[tid*33 + e] == T);
        int x = cnt;
        #pragma unroll
        for (int o = 1; o < 32; o <<= 1) {
            int y = __shfl_up_sync(0xFFFFFFFFu, x, o);
            if (lane >= o) x += y;
        }
        if (lane == 31) wsum[w] = x;
        __syncthreads();
        if (tid == 0) {
            int a = 0;
            #pragma unroll
            for (int ww = 0; ww < 8; ww++) { wbase[ww] = a; a += wsum[ww]; }
        }
        __syncthreads();
        int base = wbase[w] + x - cnt;
        int local = 0;
        #pragma unroll 4
        for (int e = 0; e < 32; e++) {
            unsigned u = keys[tid*33 + e];
            if (u == T) { if (base + local < need) s_sel[atomicAdd(&s_nsel, 1)] = tid*32 + e; local++; }
        }
        __syncthreads();
    }

    // bitonic sort 128 ascending
    for (int k = 2; k <= WSZ; k <<= 1) {
        for (int j = k >> 1; j > 0; j >>= 1) {
            if (tid < WSZ) {
                int ixj = tid ^ j;
                if (ixj > tid) {
                    int a = s_sel[tid], b = s_sel[ixj];
                    bool up = ((tid & k) == 0);
                    if ((a > b) == up) { s_sel[tid] = b; s_sel[ixj] = a; }
                }
            }
            __syncthreads();
        }
    }
    if (tid < WSZ) g_idx[row*WSZ + tid] = s_sel[tid];
}

#define SCP 132
// smem byte offsets (overlays: sc over sK; sV over sQ)
#define SM_Q    0
#define SM_K    32768
#define SM_SC   32768            // 128*132*4 = 67584 -> ends 100352
#define SM_V    0
#define SM_RINV 100352           // 128 floats
#define SM_IDX  100864
#define SMEM_ATTN (SM_IDX + WSZ*4)   // 101,376 bytes -> 2 CTAs/SM

// ---------------- K3: per-cluster attention via mma.sync tf32 ----------------
__global__ void __launch_bounds__(256, 2) k_attn(const float* __restrict__ qk,
                                                 const float* __restrict__ v,
                                                 float* __restrict__ out) {
    extern __shared__ char smem[];
    uint32_t* sQ = (uint32_t*)(smem + SM_Q);
    uint32_t* sK = (uint32_t*)(smem + SM_K);
    uint32_t* sV = (uint32_t*)(smem + SM_V);
    float*    sc = (float*)(smem + SM_SC);
    uint32_t* scU = (uint32_t*)sc;
    float*  srinv = (float*)(smem + SM_RINV);
    int*     sidx = (int*)(smem + SM_IDX);

    int tid = threadIdx.x;
    int wid = tid >> 5, lane = tid & 31;
    int g = lane >> 2, ct = lane & 3;
    int blk = blockIdx.x;
    int bh  = blk / CC;
    int h   = bh & (HH-1);
    int wm = wid >> 2, wn = wid & 3;      // 2x4 warp grid, 64x32 tiles

    if (tid < WSZ) sidx[tid] = g_idx[blk*WSZ + tid];
    __syncthreads();

    // ---- phase 1: gather + stage q, khat ----
    {
        int r = tid >> 1, kh = tid & 1, k0 = kh*32;
        int tkn = sidx[r];
        const float4* q4 = (const float4*)(qk + ((size_t)bh*TT + tkn)*DD + k0);
        float4 qv[8];
        float ss = 0.f;
        #pragma unroll
        for (int f = 0; f < 8; f++) {
            qv[f] = __ldg(q4 + f);
            ss += qv[f].x*qv[f].x + qv[f].y*qv[f].y + qv[f].z*qv[f].z + qv[f].w*qv[f].w;
        }
        ss += __shfl_xor_sync(0xFFFFFFFFu, ss, 1);
        float inv = 1.f / fmaxf(sqrtf(ss), 1e-12f);
        #pragma unroll
        for (int f = 0; f < 8; f++) {
            float e[4] = {qv[f].x, qv[f].y, qv[f].z, qv[f].w};
            #pragma unroll
            for (int u = 0; u < 4; u++) {
                int k = k0 + 4*f + u;
                sQ[QIDX(r,k)] = f2tf(e[u]);
                sK[KIDX(r,k)] = f2tf(e[u]*inv);
            }
        }
    }
    __syncthreads();

    // ---- phase 2: GEMM B (QK = q . khat^T) -> raw logits to sc ----
    {
        float acc[4][4][4];
        #pragma unroll
        for (int a = 0; a < 4; a++)
            #pragma unroll
            for (int b = 0; b < 4; b++)
                #pragma unroll
                for (int e = 0; e < 4; e++) acc[a][b][e] = 0.f;
        #pragma unroll
        for (int ks = 0; ks < 8; ks++) {
            uint32_t af[4][4]; uint32_t bf[4][2];
            #pragma unroll
            for (int mt = 0; mt < 4; mt++)
                *(uint4*)af[mt] = *(const uint4*)&sQ[(((wm*4+mt)*8+ks)*32 + lane)*4];
            #pragma unroll
            for (int nt = 0; nt < 4; nt++)
                *(uint2*)bf[nt] = *(const uint2*)&sK[(((wn*4+nt)*8+ks)*32 + lane)*2];
            #pragma unroll
            for (int mt = 0; mt < 4; mt++)
                #pragma unroll
                for (int nt = 0; nt < 4; nt++) mma8(acc[mt][nt], af[mt], bf[nt]);
        }
        __syncthreads();     // sK dead; sc (overlaying sK) safe to write
        #pragma unroll
        for (int mt = 0; mt < 4; mt++) {
            int ia = wm*64 + mt*16 + g, ib = ia + 8;
            #pragma unroll
            for (int nt = 0; nt < 4; nt++) {
                int j0 = wn*32 + nt*8 + 2*ct;
                *(float2*)&sc[ia*SCP + j0] = make_float2(acc[mt][nt][0], acc[mt][nt][1]);
                *(float2*)&sc[ib*SCP + j0] = make_float2(acc[mt][nt][2], acc[mt][nt][3]);
            }
        }
    }
    __syncthreads();

    // ---- phase 3: GEMM A (R = q . rel_w^T), B-frags via LDG (L2-hot) ----
    if (64*wm + 32*wn >= 33) {    // tiles fully j<0 skipped: (0,0),(0,1)
        const uint32_t* wf = g_wfrag + h*(WSZ*DD);
        float acc[4][4][4];
        #pragma unroll
        for (int a = 0; a < 4; a++)
            #pragma unroll
            for (int b = 0; b < 4; b++)
                #pragma unroll
                for (int e = 0; e < 4; e++) acc[a][b][e] = 0.f;
        #pragma unroll
        for (int ks = 0; ks < 8; ks++) {
            uint32_t af[4][4]; uint32_t bf[4][2];
            #pragma unroll
            for (int mt = 0; mt < 4; mt++)
                *(uint4*)af[mt] = *(const uint4*)&sQ[(((wm*4+mt)*8+ks)*32 + lane)*4];
            #pragma unroll
            for (int nt = 0; nt < 4; nt++)
                *(uint2*)bf[nt] = __ldg((const uint2*)&wf[(((wn*4+nt)*8+ks)*32 + lane)*2]);
            #pragma unroll
            for (int mt = 0; mt < 4; mt++)
                #pragma unroll
                for (int nt = 0; nt < 4; nt++) mma8(acc[mt][nt], af[mt], bf[nt]);
        }
        // j = m + i - 127; writes disjoint across warps
        #pragma unroll
        for (int mt = 0; mt < 4; mt++) {
            int ia = wm*64 + mt*16 + g, ib = ia + 8;
            #pragma unroll
            for (int nt = 0; nt < 4; nt++) {
                int m0 = wn*32 + nt*8 + 2*ct;
                int ja = m0 + ia - 127;
                if (ja   >= 0) sc[ia*SCP + ja]     += acc[mt][nt][0];
                if (ja+1 >= 0) sc[ia*SCP + ja + 1] += acc[mt][nt][1];
                int jb = m0 + ib - 127;
                if (jb   >= 0) sc[ib*SCP + jb]     += acc[mt][nt][2];
                if (jb+1 >= 0) sc[ib*SCP + jb + 1] += acc[mt][nt][3];
            }
        }
    }
    __syncthreads();

    // ---- phase 4: v gather + softmax (scale/mask fused; 1/sum deferred) ----
    {
        int r = tid >> 1, hf = tid & 1;
        int tkn = sidx[r];
        const float4* v4 = (const float4*)(v + ((size_t)bh*TT + tkn)*DD + hf*32);
        float4 vv[8];
        #pragma unroll
        for (int f = 0; f < 8; f++) vv[f] = __ldg(v4 + f);

        int i = r, j0 = hf*64;
        float mx = -1e30f;
        #pragma unroll
        for (int f = 0; f < 16; f++) {
            float4 b4 = *(const float4*)&sc[i*SCP + j0 + 4*f];
            float e[4] = {b4.x, b4.y, b4.z, b4.w};
            #pragma unroll
            for (int u = 0; u < 4; u++) {
                int j = j0 + 4*f + u;
                float val = (j == i) ? -50000.0f : e[u]*0.125f;
                mx = fmaxf(mx, val);
            }
        }
        mx = fmaxf(mx, __shfl_xor_sync(0xFFFFFFFFu, mx, 1));
        float sum = 0.f;
        #pragma unroll
        for (int f = 0; f < 16; f++) {
            float4 b4 = *(const float4*)&sc[i*SCP + j0 + 4*f];
            float e[4] = {b4.x, b4.y, b4.z, b4.w};
            uint4 o;
            uint32_t* op = (uint32_t*)&o;
            #pragma unroll
            for (int u = 0; u < 4; u++) {
                int j = j0 + 4*f + u;
                float val = (j == i) ? -50000.0f : e[u]*0.125f;
                float ex = __expf(val - mx);
                sum += ex;
                op[u] = f2tf(ex);
            }
            *(uint4*)&scU[i*SCP + j0 + 4*f] = o;
        }
        sum += __shfl_xor_sync(0xFFFFFFFFu, sum, 1);
        if (hf == 0) srinv[i] = 1.f/sum;

        // stage v frags (sV overlays sQ; dead after phase 3)
        int d0 = hf*32;
        #pragma unroll
        for (int f = 0; f < 8; f++) {
            float e[4] = {vv[f].x, vv[f].y, vv[f].z, vv[f].w};
            #pragma unroll
            for (int u = 0; u < 4; u++) sV[VIDX(r, d0 + 4*f + u)] = f2tf(e[u]);
        }
    }
    __syncthreads();

    // ---- phase 5: GEMM C (bo = attn @ v), rinv folded, red.v2 scatter ----
    {
        int wm2 = wid >> 1, wn2 = wid & 1;   // 32 rows x 32 cols per warp
        float acc[2][4][4];
        #pragma unroll
        for (int a = 0; a < 2; a++)
            #pragma unroll
            for (int b = 0; b < 4; b++)
                #pragma unroll
                for (int e = 0; e < 4; e++) acc[a][b][e] = 0.f;
        #pragma unroll
        for (int ks = 0; ks < 16; ks++) {
            uint32_t af[2][4]; uint32_t bf[4][2];
            int jr0 = 8*ks + ct;
            #pragma unroll
            for (int mt = 0; mt < 2; mt++) {
                int i0 = wm2*32 + mt*16;
                af[mt][0] = scU[(i0+g)*SCP + jr0];
                af[mt][1] = scU[(i0+g+8)*SCP + jr0];
                af[mt][2] = scU[(i0+g)*SCP + jr0+4];
                af[mt][3] = scU[(i0+g+8)*SCP + jr0+4];
            }
            #pragma unroll
            for (int dt = 0; dt < 4; dt++)
                *(uint2*)bf[dt] = *(const uint2*)&sV[(((wn2*4+dt)*16+ks)*32 + lane)*2];
            #pragma unroll
            for (int mt = 0; mt < 2; mt++)
                #pragma unroll
                for (int dt = 0; dt < 4; dt++) mma8(acc[mt][dt], af[mt], bf[dt]);
        }
        float* obase = out + (size_t)bh*TT*DD;
        #pragma unroll
        for (int mt = 0; mt < 2; mt++) {
            int ia = wm2*32 + mt*16 + g, ib = ia + 8;
            int ta = sidx[ia], tb = sidx[ib];
            float ra = srinv[ia], rb = srinv[ib];
            #pragma unroll
            for (int dt = 0; dt < 4; dt++) {
                int d0 = wn2*32 + dt*8 + 2*ct;
                red2(obase + (size_t)ta*DD + d0, acc[mt][dt][0]*ra, acc[mt][dt][1]*ra);
                red2(obase + (size_t)tb*DD + d0, acc[mt][dt][2]*rb, acc[mt][dt][3]*rb);
            }
        }
        if (tid < WSZ) atomicAdd(&g_cnt[bh*TT + sidx[tid]], 1.0f);
    }
}

// ---------------- K4: divide by counts ----------------
__global__ void k_final(float* __restrict__ out) {
    size_t i = (size_t)blockIdx.x * blockDim.x + threadIdx.x;
    if (i < (size_t)(NOUT/4)) {
        float c = g_cnt[i >> 4];
        float inv = 1.f/(c + 1e-5f);
        float4 o = ((float4*)out)[i];
        o.x *= inv; o.y *= inv; o.z *= inv; o.w *= inv;
        ((float4*)out)[i] = o;
    }
}

// ---------------- K5: loss ----------------
__global__ void k_loss(float* __restrict__ out, int out_size) {
    __shared__ float red[256];
    int tid = threadIdx.x;
    float s = 0.f;
    for (int i = tid; i < LOSSP; i += 256) s += g_losspart[i];
    red[tid] = s; __syncthreads();
    for (int st = 128; st > 0; st >>= 1) { if (tid < st) red[tid] += red[tid+st]; __syncthreads(); }
    if (tid == 0 && out_size > NOUT) out[NOUT] = red[0] * (1e-4f / (float)NOUT);
}

extern "C" void kernel_launch(void* const* d_in, const int* in_sizes, int n_in,
                              void* d_out, int out_size) {
    const float* qk    = (const float*)d_in[0];
    const float* v     = (const float*)d_in[1];
    const float* means = (const float*)d_in[2];
    const float* rel_w = (const float*)d_in[3];
    float* out = (float*)d_out;

    cudaFuncSetAttribute(k_attn, cudaFuncAttributeMaxDynamicSharedMemorySize, SMEM_ATTN);
    cudaFuncSetAttribute(k_topk, cudaFuncAttributeMaxDynamicSharedMemorySize, TK_SMEM);

    k_zero <<<(NOUT/4 + 255)/256, 256>>>(out);
    k_wprep<<<HH, 256>>>(rel_w);
    k_dists<<<dim3(TT/256, BH), 256>>>(qk, means);
    k_topk <<<BH*CC, 256, TK_SMEM>>>();
    k_attn <<<BH*CC, 256, SMEM_ATTN>>>(qk, v, out);
    k_final<<<(NOUT/4 + 255)/256, 256>>>(out);
    k_loss <<<1, 256>>>(out, out_size);
}

// round 7
// speedup vs baseline: 1.0499x; 1.0499x over previous
#include <cuda_runtime.h>
#include <math.h>
#include <stdint.h>

#define BB 4
#define HH 8
#define TT 8192
#define DD 64
#define CC 64
#define WSZ 128
#define BH (BB*HH)
#define NOUT (BB*HH*TT*DD)
#define LOSSP (BH*(TT/256))

// ---------------- scratch (device globals; no allocation) ----------------
__device__ unsigned g_keys[(size_t)BH*CC*TT];   // 64 MB sortable keys (L2-resident)
__device__ int      g_idx[BH*CC*WSZ];
__device__ float    g_cnt[BH*TT];
__device__ float    g_losspart[LOSSP];
__device__ uint32_t g_wfrag[HH*WSZ*DD];         // rel_w fragments per h (256 KB)

// ---------------- K0: zero out + cnt ----------------
__global__ void k_zero(float* __restrict__ out) {
    size_t i = (size_t)blockIdx.x * blockDim.x + threadIdx.x;
    if (i < (size_t)(NOUT/4)) ((float4*)out)[i] = make_float4(0.f,0.f,0.f,0.f);
    if (i < (size_t)(BH*TT)) g_cnt[i] = 0.f;
}

__device__ __forceinline__ unsigned fkey(float f) {
    unsigned u = __float_as_uint(f);
    return (u & 0x80000000u) ? ~u : (u | 0x80000000u);
}

// ================= mma.sync helpers (tf32, m16n8k8) =================
__device__ __forceinline__ uint32_t f2tf(float x){
    uint32_t u; asm("cvt.rna.tf32.f32 %0, %1;" : "=r"(u) : "f"(x)); return u;
}
__device__ __forceinline__ void mma8(float c[4], const uint32_t a[4], const uint32_t b[2]){
    asm volatile("mma.sync.aligned.m16n8k8.row.col.f32.tf32.tf32.f32 "
        "{%0,%1,%2,%3}, {%4,%5,%6,%7}, {%8,%9}, {%0,%1,%2,%3};"
        : "+f"(c[0]), "+f"(c[1]), "+f"(c[2]), "+f"(c[3])
        : "r"(a[0]), "r"(a[1]), "r"(a[2]), "r"(a[3]), "r"(b[0]), "r"(b[1]));
}
__device__ __forceinline__ void red2(float* p, float x, float y){
    asm volatile("red.global.add.v2.f32 [%0], {%1,%2};" :: "l"(p), "f"(x), "f"(y) : "memory");
}

// fragment staging index helpers (proven R3/R4)
#define QIDX(r,k) (((((r)>>4)*8 + ((k)>>3))*32 + (((r)&7)*4 + ((k)&3)))*4 + (((r)>>3)&1) + 2*(((k)>>2)&1))
#define KIDX(n,k) (((((n)>>3)*8 + ((k)>>3))*32 + (((n)&7)*4 + ((k)&3)))*2 + (((k)>>2)&1))
#define VIDX(j,d) (((((d)>>3)*16 + ((j)>>3))*32 + (((d)&7)*4 + ((j)&3)))*2 + (((j)>>2)&1))

// ---------------- K1: dists(keys) + loss partials ----------------
__global__ void __launch_bounds__(256) k_dists(const float* __restrict__ qk,
                                               const float* __restrict__ means) {
    int bh = blockIdx.y, h = bh & (HH-1);
    int tid = threadIdx.x;
    __shared__ float ms[CC*DD];
    for (int i = tid; i < CC*DD; i += 256) ms[i] = means[h*CC*DD + i];
    __syncthreads();

    int tok = blockIdx.x*256 + tid;
    const float4* qr = (const float4*)(qk + ((size_t)bh*TT + tok)*DD);
    float q[DD];
    float ss = 0.f;
    #pragma unroll
    for (int f = 0; f < DD/4; f++) {
        float4 a = __ldg(qr + f);
        q[4*f+0]=a.x; q[4*f+1]=a.y; q[4*f+2]=a.z; q[4*f+3]=a.w;
        ss += a.x*a.x + a.y*a.y + a.z*a.z + a.w*a.w;
    }
    float inv = 1.f / fmaxf(sqrtf(ss), 1e-12f);

    float mx = -1e30f;
    unsigned* drow = g_keys + (size_t)bh*CC*TT + tok;
    #pragma unroll 4
    for (int c = 0; c < CC; c++) {
        const float4* m4 = (const float4*)(ms + c*DD);
        float acc = 0.f;
        #pragma unroll
        for (int f = 0; f < DD/4; f++) {
            float4 m = m4[f];
            acc += q[4*f+0]*m.x + q[4*f+1]*m.y + q[4*f+2]*m.z + q[4*f+3]*m.w;
        }
        acc *= inv;
        drow[(size_t)c*TT] = fkey(acc);
        mx = fmaxf(mx, acc);
    }
    float term = ss*inv*inv + 1.0f - 2.0f*mx;

    __shared__ float red[256];
    red[tid] = term; __syncthreads();
    for (int s = 128; s > 0; s >>= 1) { if (tid < s) red[tid] += red[tid+s]; __syncthreads(); }
    if (tid == 0) g_losspart[blockIdx.y*(TT/256) + blockIdx.x] = red[0];
}

// ---------------- K1b: stage rel_w fragments per h ----------------
__global__ void k_wprep(const float* __restrict__ rel_w) {
    int h = blockIdx.x;
    int tid = threadIdx.x;
    int r = tid >> 1, kh = tid & 1, k0 = kh*32;
    const float4* w4 = (const float4*)(rel_w + ((size_t)r*HH + h)*DD + k0);
    uint32_t* dst = g_wfrag + h*(WSZ*DD);
    #pragma unroll
    for (int f = 0; f < 8; f++) {
        float4 wv = __ldg(w4 + f);
        float e[4] = {wv.x, wv.y, wv.z, wv.w};
        #pragma unroll
        for (int u = 0; u < 4; u++) dst[KIDX(r, k0 + 4*f + u)] = f2tf(e[u]);
    }
}

// ---------------- K2: top-128 per (b,h,c), sorted ascending ----------------
// dynamic smem layout (bytes) — no smem keys mirror; g_keys is L2-resident
#define TK_HIST 0                         // 2048 int = 8192
#define TK_COAR 8192                      // 256 int  = 1024
#define TK_CA   9216                      // 8192 u16 = 16384
#define TK_CB   25600                     // 8192 u16 = 16384
#define TK_SEL  41984                     // 128 int  = 512
#define TK_W    42496                     // 16 int
#define TK_SMEM 42560

__global__ void __launch_bounds__(256) k_topk() {
    extern __shared__ char tsm[];
    int* hist = (int*)(tsm + TK_HIST);
    int* coarse = (int*)(tsm + TK_COAR);
    unsigned short* candA = (unsigned short*)(tsm + TK_CA);
    unsigned short* candB = (unsigned short*)(tsm + TK_CB);
    int* s_sel = (int*)(tsm + TK_SEL);
    int* wsum = (int*)(tsm + TK_W);
    int* wbase = wsum + 8;
    __shared__ int s_bin, s_above, s_nsel, s_nc;

    int row = blockIdx.x;
    int tid = threadIdx.x;
    int lane = tid & 31, w = tid >> 5;

    for (int x = tid; x < 2048; x += 256) hist[x] = 0;
    if (tid == 0) { s_nsel = 0; s_nc = 0; }
    __syncthreads();

    // pass 1: 11-bit histogram straight from L2
    const unsigned* dr = g_keys + (size_t)row*TT;
    for (int t = tid; t < TT; t += 256) {
        unsigned u = __ldg(dr + t);
        int bin = u >> 21;
        unsigned mk = __match_any_sync(0xFFFFFFFFu, bin);
        if ((int)(__ffs(mk) - 1) == lane) atomicAdd(&hist[bin], __popc(mk));
    }
    __syncthreads();

    int cs = 0;
    #pragma unroll
    for (int e = 0; e < 8; e++) cs += hist[tid*8 + e];
    coarse[tid] = cs;
    __syncthreads();
    int need = WSZ;
    if (tid == 0) {
        int acc = 0, cb = 255;
        for (; cb > 0; cb--) { if (acc + coarse[cb] >= need) break; acc += coarse[cb]; }
        int b = cb*8 + 7;
        for (; b > cb*8; b--) { if (acc + hist[b] >= need) break; acc += hist[b]; }
        s_bin = b; s_above = acc;
    }
    __syncthreads();
    int bin1 = s_bin;
    unsigned prefix = ((unsigned)bin1) << 21;
    need -= s_above;

    // pass 2: compact winners to sel, threshold-bin indices to candA
    for (int t = tid; t < TT; t += 256) {
        unsigned u = __ldg(dr + t);
        int bin = u >> 21;
        if (bin > bin1) s_sel[atomicAdd(&s_nsel, 1)] = t;
        else if (bin == bin1) candA[atomicAdd(&s_nc, 1)] = (unsigned short)t;
    }
    __syncthreads();
    int C = s_nc;
    __syncthreads();

    unsigned short* cur = candA;
    unsigned short* nxt = candB;
    const int SH[3] = {13, 5, 0};
    const int MS[3] = {0xFF, 0xFF, 0x1F};
    #pragma unroll
    for (int p = 0; p < 3; p++) {
        if (C == need) break;          // uniform across block
        int sh = SH[p], msk = MS[p];
        if (tid <= msk) hist[tid] = 0;
        if (tid == 0) s_nc = 0;
        __syncthreads();
        for (int x = tid; x < C; x += 256) {
            unsigned u = __ldg(dr + (int)cur[x]);
            atomicAdd(&hist[(u >> sh) & msk], 1);
        }
        __syncthreads();
        if (tid == 0) {
            int acc = 0, b = msk;
            for (; b > 0; b--) { if (acc + hist[b] >= need) break; acc += hist[b]; }
            s_bin = b; s_above = acc;
        }
        __syncthreads();
        int bb = s_bin;
        prefix |= ((unsigned)bb) << sh;
        need -= s_above;
        for (int x = tid; x < C; x += 256) {
            int t = (int)cur[x];
            unsigned u = __ldg(dr + t);
            int bin = (u >> sh) & msk;
            if (bin > bb) s_sel[atomicAdd(&s_nsel, 1)] = t;
            else if (bin == bb) nxt[atomicAdd(&s_nc, 1)] = (unsigned short)t;
        }
        __syncthreads();
        C = s_nc;
        __syncthreads();
        unsigned short* tp = cur; cur = nxt; nxt = tp;
    }

    if (C == need) {
        for (int x = tid; x < C; x += 256) s_sel[atomicAdd(&s_nsel, 1)] = (int)cur[x];
        __syncthreads();
    } else {
        // rare: exact-duplicate keys == prefix; deterministic smallest-index ranks
        unsigned T = prefix;
        int cnt = 0;
        #pragma unroll 4
        for (int e = 0; e < 32; e++) cnt += (__ldg(dr + tid*32 + e) == T);
        int x = cnt;
        #pragma unroll
        for (int o = 1; o < 32; o <<= 1) {
            int y = __shfl_up_sync(0xFFFFFFFFu, x, o);
            if (lane >= o) x += y;
        }
        if (lane == 31) wsum[w] = x;
        __syncthreads();
        if (tid == 0) {
            int a = 0;
            #pragma unroll
            for (int ww = 0; ww < 8; ww++) { wbase[ww] = a; a += wsum[ww]; }
        }
        __syncthreads();
        int base = wbase[w] + x - cnt;
        int local = 0;
        #pragma unroll 4
        for (int e = 0; e < 32; e++) {
            unsigned u = __ldg(dr + tid*32 + e);
            if (u == T) { if (base + local < need) s_sel[atomicAdd(&s_nsel, 1)] = tid*32 + e; local++; }
        }
        __syncthreads();
    }

    // bitonic sort 128 ascending
    for (int k = 2; k <= WSZ; k <<= 1) {
        for (int j = k >> 1; j > 0; j >>= 1) {
            if (tid < WSZ) {
                int ixj = tid ^ j;
                if (ixj > tid) {
                    int a = s_sel[tid], b = s_sel[ixj];
                    bool up = ((tid & k) == 0);
                    if ((a > b) == up) { s_sel[tid] = b; s_sel[ixj] = a; }
                }
            }
            __syncthreads();
        }
    }
    if (tid < WSZ) g_idx[row*WSZ + tid] = s_sel[tid];
}

#define SCP 132
// smem byte offsets (overlays: sc over sK; sV over sQ)
#define SM_Q    0
#define SM_K    32768
#define SM_SC   32768            // 128*132*4 = 67584 -> ends 100352
#define SM_V    0
#define SM_RINV 100352           // 128 floats
#define SM_IDX  100864
#define SMEM_ATTN (SM_IDX + WSZ*4)   // 101,376 bytes -> 2 CTAs/SM

// ---------------- K3: per-cluster attention via mma.sync tf32 ----------------
__global__ void __launch_bounds__(256, 2) k_attn(const float* __restrict__ qk,
                                                 const float* __restrict__ v,
                                                 float* __restrict__ out) {
    extern __shared__ char smem[];
    uint32_t* sQ = (uint32_t*)(smem + SM_Q);
    uint32_t* sK = (uint32_t*)(smem + SM_K);
    uint32_t* sV = (uint32_t*)(smem + SM_V);
    float*    sc = (float*)(smem + SM_SC);
    uint32_t* scU = (uint32_t*)sc;
    float*  srinv = (float*)(smem + SM_RINV);
    int*     sidx = (int*)(smem + SM_IDX);

    int tid = threadIdx.x;
    int wid = tid >> 5, lane = tid & 31;
    int g = lane >> 2, ct = lane & 3;
    int blk = blockIdx.x;
    int bh  = blk / CC;
    int h   = bh & (HH-1);
    int wm = wid >> 2, wn = wid & 3;      // 2x4 warp grid, 64x32 tiles

    if (tid < WSZ) sidx[tid] = g_idx[blk*WSZ + tid];
    __syncthreads();

    // ---- phase 1: gather + stage q, khat ----
    {
        int r = tid >> 1, kh = tid & 1, k0 = kh*32;
        int tkn = sidx[r];
        const float4* q4 = (const float4*)(qk + ((size_t)bh*TT + tkn)*DD + k0);
        float4 qv[8];
        float ss = 0.f;
        #pragma unroll
        for (int f = 0; f < 8; f++) {
            qv[f] = __ldg(q4 + f);
            ss += qv[f].x*qv[f].x + qv[f].y*qv[f].y + qv[f].z*qv[f].z + qv[f].w*qv[f].w;
        }
        ss += __shfl_xor_sync(0xFFFFFFFFu, ss, 1);
        float inv = 1.f / fmaxf(sqrtf(ss), 1e-12f);
        #pragma unroll
        for (int f = 0; f < 8; f++) {
            float e[4] = {qv[f].x, qv[f].y, qv[f].z, qv[f].w};
            #pragma unroll
            for (int u = 0; u < 4; u++) {
                int k = k0 + 4*f + u;
                sQ[QIDX(r,k)] = f2tf(e[u]);
                sK[KIDX(r,k)] = f2tf(e[u]*inv);
            }
        }
    }
    __syncthreads();

    // ---- phase 2: GEMM B (QK = q . khat^T) -> raw logits to sc ----
    {
        float acc[4][4][4];
        #pragma unroll
        for (int a = 0; a < 4; a++)
            #pragma unroll
            for (int b = 0; b < 4; b++)
                #pragma unroll
                for (int e = 0; e < 4; e++) acc[a][b][e] = 0.f;
        #pragma unroll
        for (int ks = 0; ks < 8; ks++) {
            uint32_t af[4][4]; uint32_t bf[4][2];
            #pragma unroll
            for (int mt = 0; mt < 4; mt++)
                *(uint4*)af[mt] = *(const uint4*)&sQ[(((wm*4+mt)*8+ks)*32 + lane)*4];
            #pragma unroll
            for (int nt = 0; nt < 4; nt++)
                *(uint2*)bf[nt] = *(const uint2*)&sK[(((wn*4+nt)*8+ks)*32 + lane)*2];
            #pragma unroll
            for (int mt = 0; mt < 4; mt++)
                #pragma unroll
                for (int nt = 0; nt < 4; nt++) mma8(acc[mt][nt], af[mt], bf[nt]);
        }
        __syncthreads();     // sK dead; sc (overlaying sK) safe to write
        #pragma unroll
        for (int mt = 0; mt < 4; mt++) {
            int ia = wm*64 + mt*16 + g, ib = ia + 8;
            #pragma unroll
            for (int nt = 0; nt < 4; nt++) {
                int j0 = wn*32 + nt*8 + 2*ct;
                *(float2*)&sc[ia*SCP + j0] = make_float2(acc[mt][nt][0], acc[mt][nt][1]);
                *(float2*)&sc[ib*SCP + j0] = make_float2(acc[mt][nt][2], acc[mt][nt][3]);
            }
        }
    }
    __syncthreads();

    // ---- phase 3: GEMM A (R = q . rel_w^T), B-frags via LDG (L2-hot) ----
    if (64*wm + 32*wn >= 33) {    // tiles fully j<0 skipped: (0,0),(0,1)
        const uint32_t* wf = g_wfrag + h*(WSZ*DD);
        float acc[4][4][4];
        #pragma unroll
        for (int a = 0; a < 4; a++)
            #pragma unroll
            for (int b = 0; b < 4; b++)
                #pragma unroll
                for (int e = 0; e < 4; e++) acc[a][b][e] = 0.f;
        #pragma unroll
        for (int ks = 0; ks < 8; ks++) {
            uint32_t af[4][4]; uint32_t bf[4][2];
            #pragma unroll
            for (int mt = 0; mt < 4; mt++)
                *(uint4*)af[mt] = *(const uint4*)&sQ[(((wm*4+mt)*8+ks)*32 + lane)*4];
            #pragma unroll
            for (int nt = 0; nt < 4; nt++)
                *(uint2*)bf[nt] = __ldg((const uint2*)&wf[(((wn*4+nt)*8+ks)*32 + lane)*2]);
            #pragma unroll
            for (int mt = 0; mt < 4; mt++)
                #pragma unroll
                for (int nt = 0; nt < 4; nt++) mma8(acc[mt][nt], af[mt], bf[nt]);
        }
        // j = m + i - 127; writes disjoint across warps
        #pragma unroll
        for (int mt = 0; mt < 4; mt++) {
            int ia = wm*64 + mt*16 + g, ib = ia + 8;
            #pragma unroll
            for (int nt = 0; nt < 4; nt++) {
                int m0 = wn*32 + nt*8 + 2*ct;
                int ja = m0 + ia - 127;
                if (ja   >= 0) sc[ia*SCP + ja]     += acc[mt][nt][0];
                if (ja+1 >= 0) sc[ia*SCP + ja + 1] += acc[mt][nt][1];
                int jb = m0 + ib - 127;
                if (jb   >= 0) sc[ib*SCP + jb]     += acc[mt][nt][2];
                if (jb+1 >= 0) sc[ib*SCP + jb + 1] += acc[mt][nt][3];
            }
        }
    }
    __syncthreads();

    // ---- phase 4: v gather + softmax (scale/mask fused; 1/sum deferred) ----
    {
        int r = tid >> 1, hf = tid & 1;
        int tkn = sidx[r];
        const float4* v4 = (const float4*)(v + ((size_t)bh*TT + tkn)*DD + hf*32);
        float4 vv[8];
        #pragma unroll
        for (int f = 0; f < 8; f++) vv[f] = __ldg(v4 + f);

        int i = r, j0 = hf*64;
        float mx = -1e30f;
        #pragma unroll
        for (int f = 0; f < 16; f++) {
            float4 b4 = *(const float4*)&sc[i*SCP + j0 + 4*f];
            float e[4] = {b4.x, b4.y, b4.z, b4.w};
            #pragma unroll
            for (int u = 0; u < 4; u++) {
                int j = j0 + 4*f + u;
                float val = (j == i) ? -50000.0f : e[u]*0.125f;
                mx = fmaxf(mx, val);
            }
        }
        mx = fmaxf(mx, __shfl_xor_sync(0xFFFFFFFFu, mx, 1));
        float sum = 0.f;
        #pragma unroll
        for (int f = 0; f < 16; f++) {
            float4 b4 = *(const float4*)&sc[i*SCP + j0 + 4*f];
            float e[4] = {b4.x, b4.y, b4.z, b4.w};
            uint4 o;
            uint32_t* op = (uint32_t*)&o;
            #pragma unroll
            for (int u = 0; u < 4; u++) {
                int j = j0 + 4*f + u;
                float val = (j == i) ? -50000.0f : e[u]*0.125f;
                float ex = __expf(val - mx);
                sum += ex;
                op[u] = f2tf(ex);
            }
            *(uint4*)&scU[i*SCP + j0 + 4*f] = o;
        }
        sum += __shfl_xor_sync(0xFFFFFFFFu, sum, 1);
        if (hf == 0) srinv[i] = 1.f/sum;

        // stage v frags (sV overlays sQ; dead after phase 3)
        int d0 = hf*32;
        #pragma unroll
        for (int f = 0; f < 8; f++) {
            float e[4] = {vv[f].x, vv[f].y, vv[f].z, vv[f].w};
            #pragma unroll
            for (int u = 0; u < 4; u++) sV[VIDX(r, d0 + 4*f + u)] = f2tf(e[u]);
        }
    }
    __syncthreads();

    // ---- phase 5: GEMM C (bo = attn @ v), rinv folded, red.v2 scatter ----
    {
        int wm2 = wid >> 1, wn2 = wid & 1;   // 32 rows x 32 cols per warp
        float acc[2][4][4];
        #pragma unroll
        for (int a = 0; a < 2; a++)
            #pragma unroll
            for (int b = 0; b < 4; b++)
                #pragma unroll
                for (int e = 0; e < 4; e++) acc[a][b][e] = 0.f;
        #pragma unroll
        for (int ks = 0; ks < 16; ks++) {
            uint32_t af[2][4]; uint32_t bf[4][2];
            int jr0 = 8*ks + ct;
            #pragma unroll
            for (int mt = 0; mt < 2; mt++) {
                int i0 = wm2*32 + mt*16;
                af[mt][0] = scU[(i0+g)*SCP + jr0];
                af[mt][1] = scU[(i0+g+8)*SCP + jr0];
                af[mt][2] = scU[(i0+g)*SCP + jr0+4];
                af[mt][3] = scU[(i0+g+8)*SCP + jr0+4];
            }
            #pragma unroll
            for (int dt = 0; dt < 4; dt++)
                *(uint2*)bf[dt] = *(const uint2*)&sV[(((wn2*4+dt)*16+ks)*32 + lane)*2];
            #pragma unroll
            for (int mt = 0; mt < 2; mt++)
                #pragma unroll
                for (int dt = 0; dt < 4; dt++) mma8(acc[mt][dt], af[mt], bf[dt]);
        }
        float* obase = out + (size_t)bh*TT*DD;
        #pragma unroll
        for (int mt = 0; mt < 2; mt++) {
            int ia = wm2*32 + mt*16 + g, ib = ia + 8;
            int ta = sidx[ia], tb = sidx[ib];
            float ra = srinv[ia], rb = srinv[ib];
            #pragma unroll
            for (int dt = 0; dt < 4; dt++) {
                int d0 = wn2*32 + dt*8 + 2*ct;
                red2(obase + (size_t)ta*DD + d0, acc[mt][dt][0]*ra, acc[mt][dt][1]*ra);
                red2(obase + (size_t)tb*DD + d0, acc[mt][dt][2]*rb, acc[mt][dt][3]*rb);
            }
        }
        if (tid < WSZ) atomicAdd(&g_cnt[bh*TT + sidx[tid]], 1.0f);
    }
}

// ---------------- K4: divide by counts ----------------
__global__ void k_final(float* __restrict__ out) {
    size_t i = (size_t)blockIdx.x * blockDim.x + threadIdx.x;
    if (i < (size_t)(NOUT/4)) {
        float c = g_cnt[i >> 4];
        float inv = 1.f/(c + 1e-5f);
        float4 o = ((float4*)out)[i];
        o.x *= inv; o.y *= inv; o.z *= inv; o.w *= inv;
        ((float4*)out)[i] = o;
    }
}

// ---------------- K5: loss ----------------
__global__ void k_loss(float* __restrict__ out, int out_size) {
    __shared__ float red[256];
    int tid = threadIdx.x;
    float s = 0.f;
    for (int i = tid; i < LOSSP; i += 256) s += g_losspart[i];
    red[tid] = s; __syncthreads();
    for (int st = 128; st > 0; st >>= 1) { if (tid < st) red[tid] += red[tid+st]; __syncthreads(); }
    if (tid == 0 && out_size > NOUT) out[NOUT] = red[0] * (1e-4f / (float)NOUT);
}

extern "C" void kernel_launch(void* const* d_in, const int* in_sizes, int n_in,
                              void* d_out, int out_size) {
    const float* qk    = (const float*)d_in[0];
    const float* v     = (const float*)d_in[1];
    const float* means = (const float*)d_in[2];
    const float* rel_w = (const float*)d_in[3];
    float* out = (float*)d_out;

    cudaFuncSetAttribute(k_attn, cudaFuncAttributeMaxDynamicSharedMemorySize, SMEM_ATTN);
    cudaFuncSetAttribute(k_topk, cudaFuncAttributeMaxDynamicSharedMemorySize, TK_SMEM);

    k_zero <<<(NOUT/4 + 255)/256, 256>>>(out);
    k_wprep<<<HH, 256>>>(rel_w);
    k_dists<<<dim3(TT/256, BH), 256>>>(qk, means);
    k_topk <<<BH*CC, 256, TK_SMEM>>>();
    k_attn <<<BH*CC, 256, SMEM_ATTN>>>(qk, v, out);
    k_final<<<(NOUT/4 + 255)/256, 256>>>(out);
    k_loss <<<1, 256>>>(out, out_size);
}

// round 8
// speedup vs baseline: 1.1772x; 1.1213x over previous
#include <cuda_runtime.h>
#include <math.h>
#include <stdint.h>

#define BB 4
#define HH 8
#define TT 8192
#define DD 64
#define CC 64
#define WSZ 128
#define BH (BB*HH)
#define NOUT (BB*HH*TT*DD)
#define LOSSP (BH*(TT/256))

// ---------------- scratch (device globals; no allocation) ----------------
__device__ unsigned g_keys[(size_t)BH*CC*TT];   // 64 MB sortable keys (L2-resident)
__device__ int      g_idx[BH*CC*WSZ];
__device__ float    g_cnt[BH*TT];
__device__ float    g_losspart[LOSSP];
__device__ uint32_t g_wfrag[HH*WSZ*DD];         // rel_w fragments per h (256 KB)

// ---------------- K0: zero out + cnt ----------------
__global__ void k_zero(float* __restrict__ out) {
    size_t i = (size_t)blockIdx.x * blockDim.x + threadIdx.x;
    if (i < (size_t)(NOUT/4)) ((float4*)out)[i] = make_float4(0.f,0.f,0.f,0.f);
    if (i < (size_t)(BH*TT)) g_cnt[i] = 0.f;
}

__device__ __forceinline__ unsigned fkey(float f) {
    unsigned u = __float_as_uint(f);
    return (u & 0x80000000u) ? ~u : (u | 0x80000000u);
}

// ================= mma.sync helpers (tf32, m16n8k8) =================
__device__ __forceinline__ uint32_t f2tf(float x){
    uint32_t u; asm("cvt.rna.tf32.f32 %0, %1;" : "=r"(u) : "f"(x)); return u;
}
__device__ __forceinline__ void mma8(float c[4], const uint32_t a[4], const uint32_t b[2]){
    asm volatile("mma.sync.aligned.m16n8k8.row.col.f32.tf32.tf32.f32 "
        "{%0,%1,%2,%3}, {%4,%5,%6,%7}, {%8,%9}, {%0,%1,%2,%3};"
        : "+f"(c[0]), "+f"(c[1]), "+f"(c[2]), "+f"(c[3])
        : "r"(a[0]), "r"(a[1]), "r"(a[2]), "r"(a[3]), "r"(b[0]), "r"(b[1]));
}
__device__ __forceinline__ void red2(float* p, float x, float y){
    asm volatile("red.global.add.v2.f32 [%0], {%1,%2};" :: "l"(p), "f"(x), "f"(y) : "memory");
}

// fragment staging index helpers (proven R3/R4)
#define QIDX(r,k) (((((r)>>4)*8 + ((k)>>3))*32 + (((r)&7)*4 + ((k)&3)))*4 + (((r)>>3)&1) + 2*(((k)>>2)&1))
#define KIDX(n,k) (((((n)>>3)*8 + ((k)>>3))*32 + (((n)&7)*4 + ((k)&3)))*2 + (((k)>>2)&1))
#define VIDX(j,d) (((((d)>>3)*16 + ((j)>>3))*32 + (((d)&7)*4 + ((j)&3)))*2 + (((j)>>2)&1))

// ---------------- K1: dists(keys) + loss partials ----------------
__global__ void __launch_bounds__(256) k_dists(const float* __restrict__ qk,
                                               const float* __restrict__ means) {
    int bh = blockIdx.y, h = bh & (HH-1);
    int tid = threadIdx.x;
    __shared__ float ms[CC*DD];
    for (int i = tid; i < CC*DD; i += 256) ms[i] = means[h*CC*DD + i];
    __syncthreads();

    int tok = blockIdx.x*256 + tid;
    const float4* qr = (const float4*)(qk + ((size_t)bh*TT + tok)*DD);
    float q[DD];
    float ss = 0.f;
    #pragma unroll
    for (int f = 0; f < DD/4; f++) {
        float4 a = __ldg(qr + f);
        q[4*f+0]=a.x; q[4*f+1]=a.y; q[4*f+2]=a.z; q[4*f+3]=a.w;
        ss += a.x*a.x + a.y*a.y + a.z*a.z + a.w*a.w;
    }
    float inv = 1.f / fmaxf(sqrtf(ss), 1e-12f);

    float mx = -1e30f;
    unsigned* drow = g_keys + (size_t)bh*CC*TT + tok;
    #pragma unroll 4
    for (int c = 0; c < CC; c++) {
        const float4* m4 = (const float4*)(ms + c*DD);
        float acc = 0.f;
        #pragma unroll
        for (int f = 0; f < DD/4; f++) {
            float4 m = m4[f];
            acc += q[4*f+0]*m.x + q[4*f+1]*m.y + q[4*f+2]*m.z + q[4*f+3]*m.w;
        }
        acc *= inv;
        drow[(size_t)c*TT] = fkey(acc);
        mx = fmaxf(mx, acc);
    }
    float term = ss*inv*inv + 1.0f - 2.0f*mx;

    __shared__ float red[256];
    red[tid] = term; __syncthreads();
    for (int s = 128; s > 0; s >>= 1) { if (tid < s) red[tid] += red[tid+s]; __syncthreads(); }
    if (tid == 0) g_losspart[blockIdx.y*(TT/256) + blockIdx.x] = red[0];
}

// ---------------- K1b: stage rel_w fragments per h ----------------
__global__ void k_wprep(const float* __restrict__ rel_w) {
    int h = blockIdx.x;
    int tid = threadIdx.x;
    int r = tid >> 1, kh = tid & 1, k0 = kh*32;
    const float4* w4 = (const float4*)(rel_w + ((size_t)r*HH + h)*DD + k0);
    uint32_t* dst = g_wfrag + h*(WSZ*DD);
    #pragma unroll
    for (int f = 0; f < 8; f++) {
        float4 wv = __ldg(w4 + f);
        float e[4] = {wv.x, wv.y, wv.z, wv.w};
        #pragma unroll
        for (int u = 0; u < 4; u++) dst[KIDX(r, k0 + 4*f + u)] = f2tf(e[u]);
    }
}

// ---------------- K2: top-128 per (b,h,c), sorted ascending ----------------
// keys live in registers (32/thread, one vectorized read); candidates refined via L2
#define TK_HIST 0                         // 2048 int = 8192
#define TK_COAR 8192                      // 256 int  = 1024
#define TK_CA   9216                      // 8192 u16 = 16384
#define TK_CB   25600                     // 8192 u16 = 16384
#define TK_SEL  41984                     // 128 int  = 512
#define TK_W    42496                     // 16 int
#define TK_SMEM 42560

__global__ void __launch_bounds__(256) k_topk() {
    extern __shared__ char tsm[];
    int* hist = (int*)(tsm + TK_HIST);
    int* coarse = (int*)(tsm + TK_COAR);
    unsigned short* candA = (unsigned short*)(tsm + TK_CA);
    unsigned short* candB = (unsigned short*)(tsm + TK_CB);
    int* s_sel = (int*)(tsm + TK_SEL);
    int* wsum = (int*)(tsm + TK_W);
    int* wbase = wsum + 8;
    __shared__ int s_bin, s_above, s_nsel, s_nc;

    int row = blockIdx.x;
    int tid = threadIdx.x;
    int lane = tid & 31, w = tid >> 5;

    for (int x = tid; x < 2048; x += 256) hist[x] = 0;
    if (tid == 0) { s_nsel = 0; s_nc = 0; }

    // one vectorized read: thread owns keys[tid*32 .. +32) in registers
    const unsigned* dr = g_keys + (size_t)row*TT;
    unsigned k[32];
    {
        const uint4* b4 = (const uint4*)(dr + tid*32);
        #pragma unroll
        for (int f = 0; f < 8; f++) {
            uint4 u = __ldg(b4 + f);
            k[4*f+0]=u.x; k[4*f+1]=u.y; k[4*f+2]=u.z; k[4*f+3]=u.w;
        }
    }
    __syncthreads();

    // pass 1: 11-bit histogram from registers
    #pragma unroll 4
    for (int e = 0; e < 32; e++) atomicAdd(&hist[k[e] >> 21], 1);
    __syncthreads();

    int cs = 0;
    #pragma unroll
    for (int e = 0; e < 8; e++) cs += hist[tid*8 + e];
    coarse[tid] = cs;
    __syncthreads();
    int need = WSZ;
    if (tid == 0) {
        int acc = 0, cb = 255;
        for (; cb > 0; cb--) { if (acc + coarse[cb] >= need) break; acc += coarse[cb]; }
        int b = cb*8 + 7;
        for (; b > cb*8; b--) { if (acc + hist[b] >= need) break; acc += hist[b]; }
        s_bin = b; s_above = acc;
    }
    __syncthreads();
    int bin1 = s_bin;
    unsigned prefix = ((unsigned)bin1) << 21;
    need -= s_above;

    // pass 2: compact from registers (winners -> sel, threshold bin -> candA)
    #pragma unroll 4
    for (int e = 0; e < 32; e++) {
        int bin = k[e] >> 21;
        if (bin > bin1) s_sel[atomicAdd(&s_nsel, 1)] = tid*32 + e;
        else if (bin == bin1) candA[atomicAdd(&s_nc, 1)] = (unsigned short)(tid*32 + e);
    }
    __syncthreads();
    int C = s_nc;
    __syncthreads();

    unsigned short* cur = candA;
    unsigned short* nxt = candB;
    const int SH[3] = {13, 5, 0};
    const int MS[3] = {0xFF, 0xFF, 0x1F};
    #pragma unroll
    for (int p = 0; p < 3; p++) {
        if (C == need) break;          // uniform across block
        int sh = SH[p], msk = MS[p];
        if (tid <= msk) hist[tid] = 0;
        if (tid == 0) s_nc = 0;
        __syncthreads();
        for (int x = tid; x < C; x += 256) {
            unsigned u = __ldg(dr + (int)cur[x]);
            atomicAdd(&hist[(u >> sh) & msk], 1);
        }
        __syncthreads();
        if (tid == 0) {
            int acc = 0, b = msk;
            for (; b > 0; b--) { if (acc + hist[b] >= need) break; acc += hist[b]; }
            s_bin = b; s_above = acc;
        }
        __syncthreads();
        int bb = s_bin;
        prefix |= ((unsigned)bb) << sh;
        need -= s_above;
        for (int x = tid; x < C; x += 256) {
            int t = (int)cur[x];
            unsigned u = __ldg(dr + t);
            int bin = (u >> sh) & msk;
            if (bin > bb) s_sel[atomicAdd(&s_nsel, 1)] = t;
            else if (bin == bb) nxt[atomicAdd(&s_nc, 1)] = (unsigned short)t;
        }
        __syncthreads();
        C = s_nc;
        __syncthreads();
        unsigned short* tp = cur; cur = nxt; nxt = tp;
    }

    if (C == need) {
        for (int x = tid; x < C; x += 256) s_sel[atomicAdd(&s_nsel, 1)] = (int)cur[x];
        __syncthreads();
    } else {
        // rare: exact-duplicate keys == prefix; deterministic smallest-index ranks
        unsigned T = prefix;
        int cnt = 0;
        #pragma unroll 4
        for (int e = 0; e < 32; e++) cnt += (k[e] == T);
        int x = cnt;
        #pragma unroll
        for (int o = 1; o < 32; o <<= 1) {
            int y = __shfl_up_sync(0xFFFFFFFFu, x, o);
            if (lane >= o) x += y;
        }
        if (lane == 31) wsum[w] = x;
        __syncthreads();
        if (tid == 0) {
            int a = 0;
            #pragma unroll
            for (int ww = 0; ww < 8; ww++) { wbase[ww] = a; a += wsum[ww]; }
        }
        __syncthreads();
        int base = wbase[w] + x - cnt;
        int local = 0;
        #pragma unroll 4
        for (int e = 0; e < 32; e++) {
            if (k[e] == T) { if (base + local < need) s_sel[atomicAdd(&s_nsel, 1)] = tid*32 + e; local++; }
        }
        __syncthreads();
    }

    // bitonic sort 128 ascending
    for (int kk = 2; kk <= WSZ; kk <<= 1) {
        for (int j = kk >> 1; j > 0; j >>= 1) {
            if (tid < WSZ) {
                int ixj = tid ^ j;
                if (ixj > tid) {
                    int a = s_sel[tid], b = s_sel[ixj];
                    bool up = ((tid & kk) == 0);
                    if ((a > b) == up) { s_sel[tid] = b; s_sel[ixj] = a; }
                }
            }
            __syncthreads();
        }
    }
    if (tid < WSZ) g_idx[row*WSZ + tid] = s_sel[tid];
}

#define SCP 132
// smem byte offsets (overlays: sc over sK; sV over sQ)
#define SM_Q    0
#define SM_K    32768
#define SM_SC   32768            // 128*132*4 = 67584 -> ends 100352
#define SM_V    0
#define SM_RINV 100352           // 128 floats
#define SM_IDX  100864
#define SMEM_ATTN (SM_IDX + WSZ*4)   // 101,376 bytes -> 2 CTAs/SM

// ---------------- K3: per-cluster attention via mma.sync tf32 ----------------
__global__ void __launch_bounds__(256, 2) k_attn(const float* __restrict__ qk,
                                                 const float* __restrict__ v,
                                                 float* __restrict__ out) {
    extern __shared__ char smem[];
    uint32_t* sQ = (uint32_t*)(smem + SM_Q);
    uint32_t* sK = (uint32_t*)(smem + SM_K);
    uint32_t* sV = (uint32_t*)(smem + SM_V);
    float*    sc = (float*)(smem + SM_SC);
    uint32_t* scU = (uint32_t*)sc;
    float*  srinv = (float*)(smem + SM_RINV);
    int*     sidx = (int*)(smem + SM_IDX);

    int tid = threadIdx.x;
    int wid = tid >> 5, lane = tid & 31;
    int g = lane >> 2, ct = lane & 3;
    int blk = blockIdx.x;
    int bh  = blk / CC;
    int h   = bh & (HH-1);
    int wm = wid >> 2, wn = wid & 3;      // 2x4 warp grid, 64x32 tiles

    if (tid < WSZ) sidx[tid] = g_idx[blk*WSZ + tid];
    __syncthreads();

    // ---- phase 1: gather + stage q, khat ----
    {
        int r = tid >> 1, kh = tid & 1, k0 = kh*32;
        int tkn = sidx[r];
        const float4* q4 = (const float4*)(qk + ((size_t)bh*TT + tkn)*DD + k0);
        float4 qv[8];
        float ss = 0.f;
        #pragma unroll
        for (int f = 0; f < 8; f++) {
            qv[f] = __ldg(q4 + f);
            ss += qv[f].x*qv[f].x + qv[f].y*qv[f].y + qv[f].z*qv[f].z + qv[f].w*qv[f].w;
        }
        ss += __shfl_xor_sync(0xFFFFFFFFu, ss, 1);
        float inv = 1.f / fmaxf(sqrtf(ss), 1e-12f);
        #pragma unroll
        for (int f = 0; f < 8; f++) {
            float e[4] = {qv[f].x, qv[f].y, qv[f].z, qv[f].w};
            #pragma unroll
            for (int u = 0; u < 4; u++) {
                int k = k0 + 4*f + u;
                sQ[QIDX(r,k)] = f2tf(e[u]);
                sK[KIDX(r,k)] = f2tf(e[u]*inv);
            }
        }
    }
    __syncthreads();

    // ---- phase 2: GEMM B (QK = q . khat^T) -> raw logits to sc ----
    {
        float acc[4][4][4];
        #pragma unroll
        for (int a = 0; a < 4; a++)
            #pragma unroll
            for (int b = 0; b < 4; b++)
                #pragma unroll
                for (int e = 0; e < 4; e++) acc[a][b][e] = 0.f;
        #pragma unroll
        for (int ks = 0; ks < 8; ks++) {
            uint32_t af[4][4]; uint32_t bf[4][2];
            #pragma unroll
            for (int mt = 0; mt < 4; mt++)
                *(uint4*)af[mt] = *(const uint4*)&sQ[(((wm*4+mt)*8+ks)*32 + lane)*4];
            #pragma unroll
            for (int nt = 0; nt < 4; nt++)
                *(uint2*)bf[nt] = *(const uint2*)&sK[(((wn*4+nt)*8+ks)*32 + lane)*2];
            #pragma unroll
            for (int mt = 0; mt < 4; mt++)
                #pragma unroll
                for (int nt = 0; nt < 4; nt++) mma8(acc[mt][nt], af[mt], bf[nt]);
        }
        __syncthreads();     // sK dead; sc (overlaying sK) safe to write
        #pragma unroll
        for (int mt = 0; mt < 4; mt++) {
            int ia = wm*64 + mt*16 + g, ib = ia + 8;
            #pragma unroll
            for (int nt = 0; nt < 4; nt++) {
                int j0 = wn*32 + nt*8 + 2*ct;
                *(float2*)&sc[ia*SCP + j0] = make_float2(acc[mt][nt][0], acc[mt][nt][1]);
                *(float2*)&sc[ib*SCP + j0] = make_float2(acc[mt][nt][2], acc[mt][nt][3]);
            }
        }
    }
    __syncthreads();

    // ---- phase 3: GEMM A (R = q . rel_w^T), B-frags via LDG (L2-hot) ----
    if (64*wm + 32*wn >= 33) {    // tiles fully j<0 skipped: (0,0),(0,1)
        const uint32_t* wf = g_wfrag + h*(WSZ*DD);
        float acc[4][4][4];
        #pragma unroll
        for (int a = 0; a < 4; a++)
            #pragma unroll
            for (int b = 0; b < 4; b++)
                #pragma unroll
                for (int e = 0; e < 4; e++) acc[a][b][e] = 0.f;
        #pragma unroll
        for (int ks = 0; ks < 8; ks++) {
            uint32_t af[4][4]; uint32_t bf[4][2];
            #pragma unroll
            for (int mt = 0; mt < 4; mt++)
                *(uint4*)af[mt] = *(const uint4*)&sQ[(((wm*4+mt)*8+ks)*32 + lane)*4];
            #pragma unroll
            for (int nt = 0; nt < 4; nt++)
                *(uint2*)bf[nt] = __ldg((const uint2*)&wf[(((wn*4+nt)*8+ks)*32 + lane)*2]);
            #pragma unroll
            for (int mt = 0; mt < 4; mt++)
                #pragma unroll
                for (int nt = 0; nt < 4; nt++) mma8(acc[mt][nt], af[mt], bf[nt]);
        }
        // j = m + i - 127; writes disjoint across warps
        #pragma unroll
        for (int mt = 0; mt < 4; mt++) {
            int ia = wm*64 + mt*16 + g, ib = ia + 8;
            #pragma unroll
            for (int nt = 0; nt < 4; nt++) {
                int m0 = wn*32 + nt*8 + 2*ct;
                int ja = m0 + ia - 127;
                if (ja   >= 0) sc[ia*SCP + ja]     += acc[mt][nt][0];
                if (ja+1 >= 0) sc[ia*SCP + ja + 1] += acc[mt][nt][1];
                int jb = m0 + ib - 127;
                if (jb   >= 0) sc[ib*SCP + jb]     += acc[mt][nt][2];
                if (jb+1 >= 0) sc[ib*SCP + jb + 1] += acc[mt][nt][3];
            }
        }
    }
    __syncthreads();

    // ---- phase 4: v gather + softmax (scale/mask fused; 1/sum deferred) ----
    {
        int r = tid >> 1, hf = tid & 1;
        int tkn = sidx[r];
        const float4* v4 = (const float4*)(v + ((size_t)bh*TT + tkn)*DD + hf*32);
        float4 vv[8];
        #pragma unroll
        for (int f = 0; f < 8; f++) vv[f] = __ldg(v4 + f);

        int i = r, j0 = hf*64;
        float mx = -1e30f;
        #pragma unroll
        for (int f = 0; f < 16; f++) {
            float4 b4 = *(const float4*)&sc[i*SCP + j0 + 4*f];
            float e[4] = {b4.x, b4.y, b4.z, b4.w};
            #pragma unroll
            for (int u = 0; u < 4; u++) {
                int j = j0 + 4*f + u;
                float val = (j == i) ? -50000.0f : e[u]*0.125f;
                mx = fmaxf(mx, val);
            }
        }
        mx = fmaxf(mx, __shfl_xor_sync(0xFFFFFFFFu, mx, 1));
        float sum = 0.f;
        #pragma unroll
        for (int f = 0; f < 16; f++) {
            float4 b4 = *(const float4*)&sc[i*SCP + j0 + 4*f];
            float e[4] = {b4.x, b4.y, b4.z, b4.w};
            uint4 o;
            uint32_t* op = (uint32_t*)&o;
            #pragma unroll
            for (int u = 0; u < 4; u++) {
                int j = j0 + 4*f + u;
                float val = (j == i) ? -50000.0f : e[u]*0.125f;
                float ex = __expf(val - mx);
                sum += ex;
                op[u] = f2tf(ex);
            }
            *(uint4*)&scU[i*SCP + j0 + 4*f] = o;
        }
        sum += __shfl_xor_sync(0xFFFFFFFFu, sum, 1);
        if (hf == 0) srinv[i] = 1.f/sum;

        // stage v frags (sV overlays sQ; dead after phase 3)
        int d0 = hf*32;
        #pragma unroll
        for (int f = 0; f < 8; f++) {
            float e[4] = {vv[f].x, vv[f].y, vv[f].z, vv[f].w};
            #pragma unroll
            for (int u = 0; u < 4; u++) sV[VIDX(r, d0 + 4*f + u)] = f2tf(e[u]);
        }
    }
    __syncthreads();

    // ---- phase 5: GEMM C (bo = attn @ v), rinv folded, red.v2 scatter ----
    {
        int wm2 = wid >> 1, wn2 = wid & 1;   // 32 rows x 32 cols per warp
        float acc[2][4][4];
        #pragma unroll
        for (int a = 0; a < 2; a++)
            #pragma unroll
            for (int b = 0; b < 4; b++)
                #pragma unroll
                for (int e = 0; e < 4; e++) acc[a][b][e] = 0.f;
        #pragma unroll
        for (int ks = 0; ks < 16; ks++) {
            uint32_t af[2][4]; uint32_t bf[4][2];
            int jr0 = 8*ks + ct;
            #pragma unroll
            for (int mt = 0; mt < 2; mt++) {
                int i0 = wm2*32 + mt*16;
                af[mt][0] = scU[(i0+g)*SCP + jr0];
                af[mt][1] = scU[(i0+g+8)*SCP + jr0];
                af[mt][2] = scU[(i0+g)*SCP + jr0+4];
                af[mt][3] = scU[(i0+g+8)*SCP + jr0+4];
            }
            #pragma unroll
            for (int dt = 0; dt < 4; dt++)
                *(uint2*)bf[dt] = *(const uint2*)&sV[(((wn2*4+dt)*16+ks)*32 + lane)*2];
            #pragma unroll
            for (int mt = 0; mt < 2; mt++)
                #pragma unroll
                for (int dt = 0; dt < 4; dt++) mma8(acc[mt][dt], af[mt], bf[dt]);
        }
        float* obase = out + (size_t)bh*TT*DD;
        #pragma unroll
        for (int mt = 0; mt < 2; mt++) {
            int ia = wm2*32 + mt*16 + g, ib = ia + 8;
            int ta = sidx[ia], tb = sidx[ib];
            float ra = srinv[ia], rb = srinv[ib];
            #pragma unroll
            for (int dt = 0; dt < 4; dt++) {
                int d0 = wn2*32 + dt*8 + 2*ct;
                red2(obase + (size_t)ta*DD + d0, acc[mt][dt][0]*ra, acc[mt][dt][1]*ra);
                red2(obase + (size_t)tb*DD + d0, acc[mt][dt][2]*rb, acc[mt][dt][3]*rb);
            }
        }
        if (tid < WSZ) atomicAdd(&g_cnt[bh*TT + sidx[tid]], 1.0f);
    }
}

// ---------------- K4: divide by counts ----------------
__global__ void k_final(float* __restrict__ out) {
    size_t i = (size_t)blockIdx.x * blockDim.x + threadIdx.x;
    if (i < (size_t)(NOUT/4)) {
        float c = g_cnt[i >> 4];
        float inv = 1.f/(c + 1e-5f);
        float4 o = ((float4*)out)[i];
        o.x *= inv; o.y *= inv; o.z *= inv; o.w *= inv;
        ((float4*)out)[i] = o;
    }
}

// ---------------- K5: loss ----------------
__global__ void k_loss(float* __restrict__ out, int out_size) {
    __shared__ float red[256];
    int tid = threadIdx.x;
    float s = 0.f;
    for (int i = tid; i < LOSSP; i += 256) s += g_losspart[i];
    red[tid] = s; __syncthreads();
    for (int st = 128; st > 0; st >>= 1) { if (tid < st) red[tid] += red[tid+st]; __syncthreads(); }
    if (tid == 0 && out_size > NOUT) out[NOUT] = red[0] * (1e-4f / (float)NOUT);
}

extern "C" void kernel_launch(void* const* d_in, const int* in_sizes, int n_in,
                              void* d_out, int out_size) {
    const float* qk    = (const float*)d_in[0];
    const float* v     = (const float*)d_in[1];
    const float* means = (const float*)d_in[2];
    const float* rel_w = (const float*)d_in[3];
    float* out = (float*)d_out;

    cudaFuncSetAttribute(k_attn, cudaFuncAttributeMaxDynamicSharedMemorySize, SMEM_ATTN);
    cudaFuncSetAttribute(k_topk, cudaFuncAttributeMaxDynamicSharedMemorySize, TK_SMEM);

    k_zero <<<(NOUT/4 + 255)/256, 256>>>(out);
    k_wprep<<<HH, 256>>>(rel_w);
    k_dists<<<dim3(TT/256, BH), 256>>>(qk, means);
    k_topk <<<BH*CC, 256, TK_SMEM>>>();
    k_attn <<<BH*CC, 256, SMEM_ATTN>>>(qk, v, out);
    k_final<<<(NOUT/4 + 255)/256, 256>>>(out);
    k_loss <<<1, 256>>>(out, out_size);
}

// round 11
// speedup vs baseline: 1.2377x; 1.0514x over previous
#include <cuda_runtime.h>
#include <math.h>
#include <stdint.h>

#define BB 4
#define HH 8
#define TT 8192
#define DD 64
#define CC 64
#define WSZ 128
#define BH (BB*HH)
#define NOUT (BB*HH*TT*DD)
#define LOSSP (BH*(TT/256))

// ---------------- scratch (device globals; no allocation) ----------------
__device__ unsigned g_keys[(size_t)BH*CC*TT];   // 64 MB sortable keys (L2-resident)
__device__ int      g_idx[BH*CC*WSZ];
__device__ float    g_cnt[BH*TT];
__device__ float    g_losspart[LOSSP];
__device__ uint32_t g_wfrag[HH*WSZ*DD];         // rel_w fragments per h (256 KB)

// ---------------- K0a: zero cnt ----------------
__global__ void k_zcnt() {
    size_t i = (size_t)blockIdx.x * blockDim.x + threadIdx.x;
    if (i < (size_t)(BH*TT)) g_cnt[i] = 0.f;
}
// ---------------- K0b: zero out ----------------
__global__ void k_zout(float* __restrict__ out) {
    size_t i = (size_t)blockIdx.x * blockDim.x + threadIdx.x;
    if (i < (size_t)(NOUT/4)) ((float4*)out)[i] = make_float4(0.f,0.f,0.f,0.f);
}

__device__ __forceinline__ unsigned fkey(float f) {
    unsigned u = __float_as_uint(f);
    return (u & 0x80000000u) ? ~u : (u | 0x80000000u);
}

// ================= mma.sync helpers (tf32, m16n8k8) =================
__device__ __forceinline__ uint32_t f2tf(float x){
    uint32_t u; asm("cvt.rna.tf32.f32 %0, %1;" : "=r"(u) : "f"(x)); return u;
}
__device__ __forceinline__ void mma8(float c[4], const uint32_t a[4], const uint32_t b[2]){
    asm volatile("mma.sync.aligned.m16n8k8.row.col.f32.tf32.tf32.f32 "
        "{%0,%1,%2,%3}, {%4,%5,%6,%7}, {%8,%9}, {%0,%1,%2,%3};"
        : "+f"(c[0]), "+f"(c[1]), "+f"(c[2]), "+f"(c[3])
        : "r"(a[0]), "r"(a[1]), "r"(a[2]), "r"(a[3]), "r"(b[0]), "r"(b[1]));
}
__device__ __forceinline__ void red2(float* p, float x, float y){
    asm volatile("red.global.add.v2.f32 [%0], {%1,%2};" :: "l"(p), "f"(x), "f"(y) : "memory");
}

// fragment staging index helpers (proven R3/R4)
#define QIDX(r,k) (((((r)>>4)*8 + ((k)>>3))*32 + (((r)&7)*4 + ((k)&3)))*4 + (((r)>>3)&1) + 2*(((k)>>2)&1))
#define KIDX(n,k) (((((n)>>3)*8 + ((k)>>3))*32 + (((n)&7)*4 + ((k)&3)))*2 + (((k)>>2)&1))
#define VIDX(j,d) (((((d)>>3)*16 + ((j)>>3))*32 + (((d)&7)*4 + ((j)&3)))*2 + (((j)>>2)&1))

// ---------------- K1: dists(keys) + loss partials ----------------
__global__ void __launch_bounds__(256) k_dists(const float* __restrict__ qk,
                                               const float* __restrict__ means) {
    int bh = blockIdx.y, h = bh & (HH-1);
    int tid = threadIdx.x;
    __shared__ float ms[CC*DD];
    for (int i = tid; i < CC*DD; i += 256) ms[i] = means[h*CC*DD + i];
    __syncthreads();

    int tok = blockIdx.x*256 + tid;
    const float4* qr = (const float4*)(qk + ((size_t)bh*TT + tok)*DD);
    float q[DD];
    float ss = 0.f;
    #pragma unroll
    for (int f = 0; f < DD/4; f++) {
        float4 a = __ldg(qr + f);
        q[4*f+0]=a.x; q[4*f+1]=a.y; q[4*f+2]=a.z; q[4*f+3]=a.w;
        ss += a.x*a.x + a.y*a.y + a.z*a.z + a.w*a.w;
    }
    float inv = 1.f / fmaxf(sqrtf(ss), 1e-12f);

    float mx = -1e30f;
    unsigned* drow = g_keys + (size_t)bh*CC*TT + tok;
    #pragma unroll 4
    for (int c = 0; c < CC; c++) {
        const float4* m4 = (const float4*)(ms + c*DD);
        float acc = 0.f;
        #pragma unroll
        for (int f = 0; f < DD/4; f++) {
            float4 m = m4[f];
            acc += q[4*f+0]*m.x + q[4*f+1]*m.y + q[4*f+2]*m.z + q[4*f+3]*m.w;
        }
        acc *= inv;
        drow[(size_t)c*TT] = fkey(acc);
        mx = fmaxf(mx, acc);
    }
    float term = ss*inv*inv + 1.0f - 2.0f*mx;

    __shared__ float red[256];
    red[tid] = term; __syncthreads();
    for (int s = 128; s > 0; s >>= 1) { if (tid < s) red[tid] += red[tid+s]; __syncthreads(); }
    if (tid == 0) g_losspart[blockIdx.y*(TT/256) + blockIdx.x] = red[0];
}

// ---------------- K1b: stage rel_w fragments per h ----------------
__global__ void k_wprep(const float* __restrict__ rel_w) {
    int h = blockIdx.x;
    int tid = threadIdx.x;
    int r = tid >> 1, kh = tid & 1, k0 = kh*32;
    const float4* w4 = (const float4*)(rel_w + ((size_t)r*HH + h)*DD + k0);
    uint32_t* dst = g_wfrag + h*(WSZ*DD);
    #pragma unroll
    for (int f = 0; f < 8; f++) {
        float4 wv = __ldg(w4 + f);
        float e[4] = {wv.x, wv.y, wv.z, wv.w};
        #pragma unroll
        for (int u = 0; u < 4; u++) dst[KIDX(r, k0 + 4*f + u)] = f2tf(e[u]);
    }
}

// ---------------- K2: top-128 per (b,h,c), sorted ascending; bumps g_cnt ----------------
#define TK_HIST 0                         // 2048 int = 8192
#define TK_COAR 8192                      // 256 int  = 1024
#define TK_CA   9216                      // 8192 u16 = 16384
#define TK_CB   25600                     // 8192 u16 = 16384
#define TK_SEL  41984                     // 128 int  = 512
#define TK_W    42496                     // 16 int
#define TK_SMEM 42560

__global__ void __launch_bounds__(256) k_topk() {
    extern __shared__ char tsm[];
    int* hist = (int*)(tsm + TK_HIST);
    int* coarse = (int*)(tsm + TK_COAR);
    unsigned short* candA = (unsigned short*)(tsm + TK_CA);
    unsigned short* candB = (unsigned short*)(tsm + TK_CB);
    int* s_sel = (int*)(tsm + TK_SEL);
    int* wsum = (int*)(tsm + TK_W);
    int* wbase = wsum + 8;
    __shared__ int s_bin, s_above, s_nsel, s_nc;

    int row = blockIdx.x;
    int tid = threadIdx.x;
    int lane = tid & 31, w = tid >> 5;

    for (int x = tid; x < 2048; x += 256) hist[x] = 0;
    if (tid == 0) { s_nsel = 0; s_nc = 0; }

    // one vectorized read: thread owns keys[tid*32 .. +32) in registers (L2-hot)
    const unsigned* dr = g_keys + (size_t)row*TT;
    unsigned k[32];
    {
        const uint4* b4 = (const uint4*)(dr + tid*32);
        #pragma unroll
        for (int f = 0; f < 8; f++) {
            uint4 u = __ldg(b4 + f);
            k[4*f+0]=u.x; k[4*f+1]=u.y; k[4*f+2]=u.z; k[4*f+3]=u.w;
        }
    }
    __syncthreads();

    // pass 1: 11-bit histogram from registers
    #pragma unroll 4
    for (int e = 0; e < 32; e++) atomicAdd(&hist[k[e] >> 21], 1);
    __syncthreads();

    int cs = 0;
    #pragma unroll
    for (int e = 0; e < 8; e++) cs += hist[tid*8 + e];
    coarse[tid] = cs;
    __syncthreads();
    int need = WSZ;
    if (tid == 0) {
        int acc = 0, cb = 255;
        for (; cb > 0; cb--) { if (acc + coarse[cb] >= need) break; acc += coarse[cb]; }
        int b = cb*8 + 7;
        for (; b > cb*8; b--) { if (acc + hist[b] >= need) break; acc += hist[b]; }
        s_bin = b; s_above = acc;
    }
    __syncthreads();
    int bin1 = s_bin;
    unsigned prefix = ((unsigned)bin1) << 21;
    need -= s_above;

    // pass 2: compact from registers
    #pragma unroll 4
    for (int e = 0; e < 32; e++) {
        int bin = k[e] >> 21;
        if (bin > bin1) s_sel[atomicAdd(&s_nsel, 1)] = tid*32 + e;
        else if (bin == bin1) candA[atomicAdd(&s_nc, 1)] = (unsigned short)(tid*32 + e);
    }
    __syncthreads();
    int C = s_nc;
    __syncthreads();

    unsigned short* cur = candA;
    unsigned short* nxt = candB;
    const int SH[3] = {13, 5, 0};
    const int MS[3] = {0xFF, 0xFF, 0x1F};
    #pragma unroll
    for (int p = 0; p < 3; p++) {
        if (C == need) break;          // uniform across block
        int sh = SH[p], msk = MS[p];
        if (tid <= msk) hist[tid] = 0;
        if (tid == 0) s_nc = 0;
        __syncthreads();
        for (int x = tid; x < C; x += 256) {
            unsigned u = __ldg(dr + (int)cur[x]);
            atomicAdd(&hist[(u >> sh) & msk], 1);
        }
        __syncthreads();
        if (tid == 0) {
            int acc = 0, b = msk;
            for (; b > 0; b--) { if (acc + hist[b] >= need) break; acc += hist[b]; }
            s_bin = b; s_above = acc;
        }
        __syncthreads();
        int bb = s_bin;
        prefix |= ((unsigned)bb) << sh;
        need -= s_above;
        for (int x = tid; x < C; x += 256) {
            int t = (int)cur[x];
            unsigned u = __ldg(dr + t);
            int bin = (u >> sh) & msk;
            if (bin > bb) s_sel[atomicAdd(&s_nsel, 1)] = t;
            else if (bin == bb) nxt[atomicAdd(&s_nc, 1)] = (unsigned short)t;
        }
        __syncthreads();
        C = s_nc;
        __syncthreads();
        unsigned short* tp = cur; cur = nxt; nxt = tp;
    }

    if (C == need) {
        for (int x = tid; x < C; x += 256) s_sel[atomicAdd(&s_nsel, 1)] = (int)cur[x];
        __syncthreads();
    } else {
        // rare: exact-duplicate keys == prefix; deterministic smallest-index ranks
        unsigned T = prefix;
        int cnt = 0;
        #pragma unroll 4
        for (int e = 0; e < 32; e++) cnt += (k[e] == T);
        int x = cnt;
        #pragma unroll
        for (int o = 1; o < 32; o <<= 1) {
            int y = __shfl_up_sync(0xFFFFFFFFu, x, o);
            if (lane >= o) x += y;
        }
        if (lane == 31) wsum[w] = x;
        __syncthreads();
        if (tid == 0) {
            int a = 0;
            #pragma unroll
            for (int ww = 0; ww < 8; ww++) { wbase[ww] = a; a += wsum[ww]; }
        }
        __syncthreads();
        int base = wbase[w] + x - cnt;
        int local = 0;
        #pragma unroll 4
        for (int e = 0; e < 32; e++) {
            if (k[e] == T) { if (base + local < need) s_sel[atomicAdd(&s_nsel, 1)] = tid*32 + e; local++; }
        }
        __syncthreads();
    }

    // bitonic sort 128 ascending
    for (int kk = 2; kk <= WSZ; kk <<= 1) {
        for (int j = kk >> 1; j > 0; j >>= 1) {
            if (tid < WSZ) {
                int ixj = tid ^ j;
                if (ixj > tid) {
                    int a = s_sel[tid], b = s_sel[ixj];
                    bool up = ((tid & kk) == 0);
                    if ((a > b) == up) { s_sel[tid] = b; s_sel[ixj] = a; }
                }
            }
            __syncthreads();
        }
    }
    if (tid < WSZ) {
        g_idx[row*WSZ + tid] = s_sel[tid];
        atomicAdd(&g_cnt[(row/CC)*TT + s_sel[tid]], 1.0f);
    }
}

#define SCP 132
// smem byte offsets (overlays: sc over sK; sV over sQ)
#define SM_Q    0
#define SM_K    32768
#define SM_SC   32768            // 128*132*4 = 67584 -> ends 100352
#define SM_V    0
#define SM_RINV 100352           // 128 floats
#define SM_IDX  100864
#define SMEM_ATTN (SM_IDX + WSZ*4)   // 101,376 bytes -> 2 CTAs/SM

// ---------------- K3: per-cluster attention via mma.sync tf32 ----------------
__global__ void __launch_bounds__(256, 2) k_attn(const float* __restrict__ qk,
                                                 const float* __restrict__ v,
                                                 float* __restrict__ out) {
    extern __shared__ char smem[];
    uint32_t* sQ = (uint32_t*)(smem + SM_Q);
    uint32_t* sK = (uint32_t*)(smem + SM_K);
    uint32_t* sV = (uint32_t*)(smem + SM_V);
    float*    sc = (float*)(smem + SM_SC);
    uint32_t* scU = (uint32_t*)sc;
    float*  srinv = (float*)(smem + SM_RINV);
    int*     sidx = (int*)(smem + SM_IDX);

    int tid = threadIdx.x;
    int wid = tid >> 5, lane = tid & 31;
    int g = lane >> 2, ct = lane & 3;
    int blk = blockIdx.x;
    int bh  = blk / CC;
    int h   = bh & (HH-1);
    int wm = wid >> 2, wn = wid & 3;      // 2x4 warp grid, 64x32 tiles

    if (tid < WSZ) sidx[tid] = g_idx[blk*WSZ + tid];
    __syncthreads();

    // ---- phase 1: gather + stage q, khat ----
    {
        int r = tid >> 1, kh = tid & 1, k0 = kh*32;
        int tkn = sidx[r];
        const float4* q4 = (const float4*)(qk + ((size_t)bh*TT + tkn)*DD + k0);
        float4 qv[8];
        float ss = 0.f;
        #pragma unroll
        for (int f = 0; f < 8; f++) {
            qv[f] = __ldg(q4 + f);
            ss += qv[f].x*qv[f].x + qv[f].y*qv[f].y + qv[f].z*qv[f].z + qv[f].w*qv[f].w;
        }
        ss += __shfl_xor_sync(0xFFFFFFFFu, ss, 1);
        float inv = 1.f / fmaxf(sqrtf(ss), 1e-12f);
        #pragma unroll
        for (int f = 0; f < 8; f++) {
            float e[4] = {qv[f].x, qv[f].y, qv[f].z, qv[f].w};
            #pragma unroll
            for (int u = 0; u < 4; u++) {
                int k = k0 + 4*f + u;
                sQ[QIDX(r,k)] = f2tf(e[u]);
                sK[KIDX(r,k)] = f2tf(e[u]*inv);
            }
        }
    }
    __syncthreads();

    // ---- phase 2: GEMM B (QK = q . khat^T) -> raw logits to sc ----
    {
        float acc[4][4][4];
        #pragma unroll
        for (int a = 0; a < 4; a++)
            #pragma unroll
            for (int b = 0; b < 4; b++)
                #pragma unroll
                for (int e = 0; e < 4; e++) acc[a][b][e] = 0.f;
        #pragma unroll
        for (int ks = 0; ks < 8; ks++) {
            uint32_t af[4][4]; uint32_t bf[4][2];
            #pragma unroll
            for (int mt = 0; mt < 4; mt++)
                *(uint4*)af[mt] = *(const uint4*)&sQ[(((wm*4+mt)*8+ks)*32 + lane)*4];
            #pragma unroll
            for (int nt = 0; nt < 4; nt++)
                *(uint2*)bf[nt] = *(const uint2*)&sK[(((wn*4+nt)*8+ks)*32 + lane)*2];
            #pragma unroll
            for (int mt = 0; mt < 4; mt++)
                #pragma unroll
                for (int nt = 0; nt < 4; nt++) mma8(acc[mt][nt], af[mt], bf[nt]);
        }
        __syncthreads();     // sK dead; sc (overlaying sK) safe to write
        #pragma unroll
        for (int mt = 0; mt < 4; mt++) {
            int ia = wm*64 + mt*16 + g, ib = ia + 8;
            #pragma unroll
            for (int nt = 0; nt < 4; nt++) {
                int j0 = wn*32 + nt*8 + 2*ct;
                *(float2*)&sc[ia*SCP + j0] = make_float2(acc[mt][nt][0], acc[mt][nt][1]);
                *(float2*)&sc[ib*SCP + j0] = make_float2(acc[mt][nt][2], acc[mt][nt][3]);
            }
        }
    }
    __syncthreads();

    // ---- phase 3: GEMM A (R = q . rel_w^T), B-frags via LDG (L2-hot) ----
    if (64*wm + 32*wn >= 33) {    // tiles fully j<0 skipped: (0,0),(0,1)
        const uint32_t* wf = g_wfrag + h*(WSZ*DD);
        float acc[4][4][4];
        #pragma unroll
        for (int a = 0; a < 4; a++)
            #pragma unroll
            for (int b = 0; b < 4; b++)
                #pragma unroll
                for (int e = 0; e < 4; e++) acc[a][b][e] = 0.f;
        #pragma unroll
        for (int ks = 0; ks < 8; ks++) {
            uint32_t af[4][4]; uint32_t bf[4][2];
            #pragma unroll
            for (int mt = 0; mt < 4; mt++)
                *(uint4*)af[mt] = *(const uint4*)&sQ[(((wm*4+mt)*8+ks)*32 + lane)*4];
            #pragma unroll
            for (int nt = 0; nt < 4; nt++)
                *(uint2*)bf[nt] = __ldg((const uint2*)&wf[(((wn*4+nt)*8+ks)*32 + lane)*2]);
            #pragma unroll
            for (int mt = 0; mt < 4; mt++)
                #pragma unroll
                for (int nt = 0; nt < 4; nt++) mma8(acc[mt][nt], af[mt], bf[nt]);
        }
        // j = m + i - 127; writes disjoint across warps
        #pragma unroll
        for (int mt = 0; mt < 4; mt++) {
            int ia = wm*64 + mt*16 + g, ib = ia + 8;
            #pragma unroll
            for (int nt = 0; nt < 4; nt++) {
                int m0 = wn*32 + nt*8 + 2*ct;
                int ja = m0 + ia - 127;
                if (ja   >= 0) sc[ia*SCP + ja]     += acc[mt][nt][0];
                if (ja+1 >= 0) sc[ia*SCP + ja + 1] += acc[mt][nt][1];
                int jb = m0 + ib - 127;
                if (jb   >= 0) sc[ib*SCP + jb]     += acc[mt][nt][2];
                if (jb+1 >= 0) sc[ib*SCP + jb + 1] += acc[mt][nt][3];
            }
        }
    }
    __syncthreads();

    // ---- phase 4: v gather + softmax (scale/mask fused; 1/sum and 1/cnt deferred) ----
    {
        int r = tid >> 1, hf = tid & 1;
        int tkn = sidx[r];
        const float4* v4 = (const float4*)(v + ((size_t)bh*TT + tkn)*DD + hf*32);
        float cntv = (hf == 0) ? __ldg(&g_cnt[bh*TT + tkn]) : 0.f;
        float4 vv[8];
        #pragma unroll
        for (int f = 0; f < 8; f++) vv[f] = __ldg(v4 + f);

        int i = r, j0 = hf*64;
        float mx = -1e30f;
        #pragma unroll
        for (int f = 0; f < 16; f++) {
            float4 b4 = *(const float4*)&sc[i*SCP + j0 + 4*f];
            float e[4] = {b4.x, b4.y, b4.z, b4.w};
            #pragma unroll
            for (int u = 0; u < 4; u++) {
                int j = j0 + 4*f + u;
                float val = (j == i) ? -50000.0f : e[u]*0.125f;
                mx = fmaxf(mx, val);
            }
        }
        mx = fmaxf(mx, __shfl_xor_sync(0xFFFFFFFFu, mx, 1));
        float sum = 0.f;
        #pragma unroll
        for (int f = 0; f < 16; f++) {
            float4 b4 = *(const float4*)&sc[i*SCP + j0 + 4*f];
            float e[4] = {b4.x, b4.y, b4.z, b4.w};
            uint4 o;
            uint32_t* op = (uint32_t*)&o;
            #pragma unroll
            for (int u = 0; u < 4; u++) {
                int j = j0 + 4*f + u;
                float val = (j == i) ? -50000.0f : e[u]*0.125f;
                float ex = __expf(val - mx);
                sum += ex;
                op[u] = f2tf(ex);
            }
            *(uint4*)&scU[i*SCP + j0 + 4*f] = o;
        }
        sum += __shfl_xor_sync(0xFFFFFFFFu, sum, 1);
        if (hf == 0) srinv[i] = 1.f/(sum*(cntv + 1e-5f));

        // stage v frags (sV overlays sQ; dead after phase 3)
        int d0 = hf*32;
        #pragma unroll
        for (int f = 0; f < 8; f++) {
            float e[4] = {vv[f].x, vv[f].y, vv[f].z, vv[f].w};
            #pragma unroll
            for (int u = 0; u < 4; u++) sV[VIDX(r, d0 + 4*f + u)] = f2tf(e[u]);
        }
    }
    __syncthreads();

    // ---- phase 5: GEMM C (bo = attn @ v), rinv folded, red.v2 scatter ----
    {
        int wm2 = wid >> 1, wn2 = wid & 1;   // 32 rows x 32 cols per warp
        float acc[2][4][4];
        #pragma unroll
        for (int a = 0; a < 2; a++)
            #pragma unroll
            for (int b = 0; b < 4; b++)
                #pragma unroll
                for (int e = 0; e < 4; e++) acc[a][b][e] = 0.f;
        #pragma unroll
        for (int ks = 0; ks < 16; ks++) {
            uint32_t af[2][4]; uint32_t bf[4][2];
            int jr0 = 8*ks + ct;
            #pragma unroll
            for (int mt = 0; mt < 2; mt++) {
                int i0 = wm2*32 + mt*16;
                af[mt][0] = scU[(i0+g)*SCP + jr0];
                af[mt][1] = scU[(i0+g+8)*SCP + jr0];
                af[mt][2] = scU[(i0+g)*SCP + jr0+4];
                af[mt][3] = scU[(i0+g+8)*SCP + jr0+4];
            }
            #pragma unroll
            for (int dt = 0; dt < 4; dt++)
                *(uint2*)bf[dt] = *(const uint2*)&sV[(((wn2*4+dt)*16+ks)*32 + lane)*2];
            #pragma unroll
            for (int mt = 0; mt < 2; mt++)
                #pragma unroll
                for (int dt = 0; dt < 4; dt++) mma8(acc[mt][dt], af[mt], bf[dt]);
        }
        float* obase = out + (size_t)bh*TT*DD;
        #pragma unroll
        for (int mt = 0; mt < 2; mt++) {
            int ia = wm2*32 + mt*16 + g, ib = ia + 8;
            int ta = sidx[ia], tb = sidx[ib];
            float ra = srinv[ia], rb = srinv[ib];
            #pragma unroll
            for (int dt = 0; dt < 4; dt++) {
                int d0 = wn2*32 + dt*8 + 2*ct;
                red2(obase + (size_t)ta*DD + d0, acc[mt][dt][0]*ra, acc[mt][dt][1]*ra);
                red2(obase + (size_t)tb*DD + d0, acc[mt][dt][2]*rb, acc[mt][dt][3]*rb);
            }
        }
    }
}

// ---------------- K5: loss ----------------
__global__ void k_loss(float* __restrict__ out, int out_size) {
    __shared__ float red[256];
    int tid = threadIdx.x;
    float s = 0.f;
    for (int i = tid; i < LOSSP; i += 256) s += g_losspart[i];
    red[tid] = s; __syncthreads();
    for (int st = 128; st > 0; st >>= 1) { if (tid < st) red[tid] += red[tid+st]; __syncthreads(); }
    if (tid == 0 && out_size > NOUT) out[NOUT] = red[0] * (1e-4f / (float)NOUT);
}

extern "C" void kernel_launch(void* const* d_in, const int* in_sizes, int n_in,
                              void* d_out, int out_size) {
    const float* qk    = (const float*)d_in[0];
    const float* v     = (const float*)d_in[1];
    const float* means = (const float*)d_in[2];
    const float* rel_w = (const float*)d_in[3];
    float* out = (float*)d_out;

    cudaFuncSetAttribute(k_attn, cudaFuncAttributeMaxDynamicSharedMemorySize, SMEM_ATTN);
    cudaFuncSetAttribute(k_topk, cudaFuncAttributeMaxDynamicSharedMemorySize, TK_SMEM);

    k_zcnt <<<(BH*TT + 255)/256, 256>>>();
    k_wprep<<<HH, 256>>>(rel_w);
    k_dists<<<dim3(TT/256, BH), 256>>>(qk, means);
    k_topk <<<BH*CC, 256, TK_SMEM>>>();
    k_zout <<<(NOUT/4 + 255)/256, 256>>>(out);
    k_attn <<<BH*CC, 256, SMEM_ATTN>>>(qk, v, out);
    k_loss <<<1, 256>>>(out, out_size);
}